// round 12
// baseline (speedup 1.0000x reference)
#include <cuda_runtime.h>

#define NN 524288
#define EE 4194304
#define BB 4096
#define HH 32
#define KK 30
#define CAP 512
#define MAXZ1 1001
#define EPSF 1e-5f
#define NBLK 2048          // NN/256

// ---------------- scratch (device globals; no allocation allowed) ----------
__device__ int   g_deg[NN];
__device__ float g_dinv[NN];
__device__ int2  g_pack[NN];              // {xz, dinv bits}
__device__ float g_embw[MAXZ1 * HH];      // emb @ W0   (128KB)
__device__ float g_ha[(size_t)NN * HH];   // layer1 out
__device__ float g_hb[(size_t)NN * HH];   // layer0 out
__device__ float g_c31[NN];               // h' channel 31 sidecar (L2-resident)
__device__ unsigned g_key[NN];
__device__ int   g_rowstart[NN + 1];
__device__ int   g_cursor[NN];
__device__ int   g_csrsrc[EE];
__device__ int   g_bsum[NBLK];
__device__ int   g_start2[BB + 1];
__device__ int   g_sel[BB * KK];
__device__ float g_pooled[(size_t)BB * KK * HH];

__device__ __forceinline__ float4 add4(float4 a, float4 b) {
    return make_float4(a.x + b.x, a.y + b.y, a.z + b.z, a.w + b.w);
}
__device__ __forceinline__ float4 scale4(float4 a, float s) {
    return make_float4(a.x * s, a.y * s, a.z * s, a.w * s);
}
__device__ __forceinline__ unsigned long long pk2(float x, float y) {
    unsigned long long r;
    asm("mov.b64 %0, {%1,%2};" : "=l"(r) : "f"(x), "f"(y));
    return r;
}
__device__ __forceinline__ void fma2(unsigned long long& d, unsigned long long a,
                                     unsigned long long b) {
    asm("fma.rn.f32x2 %0, %1, %2, %0;" : "+l"(d) : "l"(a), "l"(b));
}
__device__ __forceinline__ unsigned long long mul2(unsigned long long a,
                                                   unsigned long long b) {
    unsigned long long r;
    asm("mul.rn.f32x2 %0, %1, %2;" : "=l"(r) : "l"(a), "l"(b));
    return r;
}

// ---------------- embW0 = emb @ Wc[0], fused with g_deg zeroing -------------
__global__ void __launch_bounds__(256) k_embw(
    const float* __restrict__ emb, const float* __restrict__ Wc)
{
    __shared__ float Ws[HH * HH];
    int t = threadIdx.x;
    int b = blockIdx.x;
    g_deg[b * 256 + t] = 0;
    if (b < 126) {
        for (int i = t; i < HH * HH; i += 256) Ws[i] = Wc[i];
        __syncthreads();
        int row = b * 8 + (t >> 5);
        int col = t & 31;
        if (row < MAXZ1) {
            const float* er = emb + (size_t)row * HH;
            float acc = 0.f;
#pragma unroll
            for (int k = 0; k < HH; k++) acc = fmaf(er[k], Ws[k * HH + col], acc);
            g_embw[row * HH + col] = acc;
        }
    }
}

// in-degree histogram + graph-boundary detection (batch is sorted)
__global__ void k_degb(const int* __restrict__ dst, const int* __restrict__ batch) {
    int i = blockIdx.x * 256 + threadIdx.x;   // grid covers EE
    atomicAdd(&g_deg[dst[i]], 1);
    if (i < NN) {
        int b1 = batch[i];
        int b0 = (i > 0) ? batch[i - 1] : -1;
        for (int b = b0 + 1; b <= b1; b++) g_start2[b] = i;
        if (i == NN - 1)
            for (int b = b1 + 1; b <= BB; b++) g_start2[b] = NN;
    }
}

// scanA: block sums of deg + dinv + pack{xz,dinv}
__global__ void k_scanA(const int* __restrict__ xz) {
    __shared__ int s[256];
    int t = threadIdx.x;
    int i = blockIdx.x * 256 + t;
    int d = g_deg[i];
    float dn = rsqrtf((float)d + 1.0f);
    g_dinv[i] = dn;
    g_pack[i] = make_int2(xz[i], __float_as_int(dn));
    s[t] = d;
    __syncthreads();
    for (int off = 128; off; off >>= 1) {
        if (t < off) s[t] += s[t + off];
        __syncthreads();
    }
    if (t == 0) g_bsum[blockIdx.x] = s[0];
}

// scanB: each block sums its bsum prefix directly, then local scan
__global__ void __launch_bounds__(256) k_scanB() {
    __shared__ int red[256];
    __shared__ int s[256];
    int b = blockIdx.x, t = threadIdx.x;
    int part = 0;
    for (int j = t; j < b; j += 256) part += g_bsum[j];
    red[t] = part;
    __syncthreads();
    for (int off = 128; off; off >>= 1) {
        if (t < off) red[t] += red[t + off];
        __syncthreads();
    }
    int base = red[0];
    int i = b * 256 + t;
    int d = g_deg[i];
    s[t] = d;
    __syncthreads();
    for (int off = 1; off < 256; off <<= 1) {
        int v = (t >= off) ? s[t - off] : 0;
        __syncthreads();
        s[t] += v;
        __syncthreads();
    }
    int excl = base + s[t] - d;
    g_rowstart[i] = excl;
    g_cursor[i] = excl;
    if (i == NN - 1) g_rowstart[NN] = EE;
}

// ---------------- CSR fill: src values (slot order nondeterministic) --------
__global__ void k_fill(const int* __restrict__ src, const int* __restrict__ dst) {
    int e = blockIdx.x * 256 + threadIdx.x;   // grid covers EE
    int d = dst[e];
    int pos = atomicAdd(&g_cursor[d], 1);
    g_csrsrc[pos] = src[e];
}

// ---------------- canonicalize rows: sort src values ascending --------------
__global__ void __launch_bounds__(256) k_sortval() {
    int n = blockIdx.x * 256 + threadIdx.x;
    int beg = g_rowstart[n];
    int len = g_rowstart[n + 1] - beg;
    if (len <= 1) return;
    if (len <= 16) {
        int v[16];
#pragma unroll
        for (int i = 0; i < 16; i++)
            v[i] = (i < len) ? g_csrsrc[beg + i] : 0x7FFFFFFF;
#pragma unroll
        for (int k = 2; k <= 16; k <<= 1) {
#pragma unroll
            for (int j = k >> 1; j > 0; j >>= 1) {
#pragma unroll
                for (int i = 0; i < 16; i++) {
                    int ix = i ^ j;
                    if (ix > i) {
                        bool up = ((i & k) == 0);
                        int a = v[i], c = v[ix];
                        bool sw = up ? (a > c) : (a < c);
                        if (sw) { v[i] = c; v[ix] = a; }
                    }
                }
            }
        }
        for (int i = 0; i < len; i++) g_csrsrc[beg + i] = v[i];
    } else {
        int end = beg + len;
        for (int i = beg + 1; i < end; i++) {
            int key = g_csrsrc[i];
            int j = i - 1;
            while (j >= beg && g_csrsrc[j] > key) {
                g_csrsrc[j + 1] = g_csrsrc[j];
                j--;
            }
            g_csrsrc[j + 1] = key;
        }
    }
}

// ---------------- layer 0 fused: table-gather + BN0 + ReLU + GEMM1 ----------
// 8 thr/node; warp-local sync; predicated independent tail loads.
__global__ void __launch_bounds__(256) k_gbg0(
    const float* __restrict__ Wc, const float* __restrict__ bcp,
    const float* __restrict__ gamma, const float* __restrict__ beta,
    const float* __restrict__ rmean, const float* __restrict__ rvar)
{
    __shared__ ulonglong2 Ws2[HH * 8];
    __shared__ float sA[HH], sB[HH];
    __shared__ float xs[32 * 40];
    int t = threadIdx.x;
    if (t < HH * 8) Ws2[t] = ((const ulonglong2*)(Wc + 1 * HH * HH))[t];
    if (t < HH) {
        float sc = gamma[t] * rsqrtf(rvar[t] + EPSF);
        float sh = beta[t] - rmean[t] * sc;
        sA[t] = sc;
        sB[t] = fmaf(bcp[t], sc, sh);
    }
    __syncthreads();

    int tid = blockIdx.x * 256 + t;   // grid covers NN*8
    int n = tid >> 3;
    int p = tid & 7;
    int nl = t >> 3;
    const float4* ew = (const float4*)g_embw;

    int beg = __ldg(&g_rowstart[n]);
    int end = __ldg(&g_rowstart[n + 1]);

    // self term: load early (overlaps edge loads), ADD LAST (order preserved)
    int2 pks = __ldg(&g_pack[n]);
    float dn = __int_as_float(pks.y);
    float4 selfv = scale4(__ldg(ew + (size_t)pks.x * 8 + p), dn);

    float4 acc = make_float4(0.f, 0.f, 0.f, 0.f);
    int r = beg;
    while (r + 8 <= end) {
        int idx[8];
#pragma unroll
        for (int j = 0; j < 8; j++) idx[j] = __ldcs(&g_csrsrc[r + j]);
        int2 pk[8];
#pragma unroll
        for (int j = 0; j < 8; j++) pk[j] = __ldg(&g_pack[idx[j]]);
        float4 hv[8];
#pragma unroll
        for (int j = 0; j < 8; j++)
            hv[j] = scale4(__ldg(ew + (size_t)pk[j].x * 8 + p),
                           __int_as_float(pk[j].y));
        acc = add4(acc, add4(add4(add4(hv[0], hv[1]), add4(hv[2], hv[3])),
                             add4(add4(hv[4], hv[5]), add4(hv[6], hv[7]))));
        r += 8;
    }
    {   // tail m in [0,7]: independent predicated loads, same add grouping
        int m = end - r;
        int idx[7]; int2 pk[7]; float4 hv[7];
#pragma unroll
        for (int j = 0; j < 7; j++) if (j < m) idx[j] = __ldcs(&g_csrsrc[r + j]);
#pragma unroll
        for (int j = 0; j < 7; j++) if (j < m) pk[j] = __ldg(&g_pack[idx[j]]);
#pragma unroll
        for (int j = 0; j < 7; j++)
            if (j < m) hv[j] = scale4(__ldg(ew + (size_t)pk[j].x * 8 + p),
                                      __int_as_float(pk[j].y));
        int s0 = 0;
        if (m >= 4) {
            acc = add4(acc, add4(add4(hv[0], hv[1]), add4(hv[2], hv[3])));
            s0 = 4;
        }
#pragma unroll
        for (int j = 0; j < 7; j++)
            if (j >= s0 && j < m) acc = add4(acc, hv[j]);
    }
    acc = add4(acc, selfv);   // self last

    float4 xv;
    xv.x = fmaxf(fmaf(acc.x * dn, sA[4 * p + 0], sB[4 * p + 0]), 0.f);
    xv.y = fmaxf(fmaf(acc.y * dn, sA[4 * p + 1], sB[4 * p + 1]), 0.f);
    xv.z = fmaxf(fmaf(acc.z * dn, sA[4 * p + 2], sB[4 * p + 2]), 0.f);
    xv.w = fmaxf(fmaf(acc.w * dn, sA[4 * p + 3], sB[4 * p + 3]), 0.f);
    *(float4*)(xs + nl * 40 + 4 * p) = xv;
    __syncwarp();

    float xrf[HH];
    {
        const float4* xrp = (const float4*)(xs + nl * 40);
#pragma unroll
        for (int q = 0; q < 8; q++) {
            float4 v = xrp[q];
            xrf[4 * q + 0] = v.x; xrf[4 * q + 1] = v.y;
            xrf[4 * q + 2] = v.z; xrf[4 * q + 3] = v.w;
        }
    }
    unsigned long long a0 = 0ULL, a1 = 0ULL;
#pragma unroll
    for (int k = 0; k < HH; k++) {
        unsigned long long xkk = pk2(xrf[k], xrf[k]);
        ulonglong2 w = Ws2[k * 8 + p];
        fma2(a0, xkk, w.x);
        fma2(a1, xkk, w.y);
    }
    unsigned long long dn2 = pk2(dn, dn);
    ((ulonglong2*)(g_hb + (size_t)n * HH))[p] =
        make_ulonglong2(mul2(a0, dn2), mul2(a1, dn2));
}

// ---------------- layer 1 fused: gather(hb) + BN1 + ReLU + GEMM2 -> ha ------
// Also writes channel-31 sidecar g_c31 (bit-identical value).
__global__ void __launch_bounds__(256) k_gbg(
    const float* __restrict__ Wc, const float* __restrict__ bcp,
    const float* __restrict__ gamma, const float* __restrict__ beta,
    const float* __restrict__ rmean, const float* __restrict__ rvar)
{
    __shared__ ulonglong2 Ws2[HH * 8];
    __shared__ float sA[HH], sB[HH];
    __shared__ float xs[32 * 40];
    int t = threadIdx.x;
    if (t < HH * 8) Ws2[t] = ((const ulonglong2*)(Wc + 2 * HH * HH))[t];
    if (t < HH) {
        float sc = gamma[HH + t] * rsqrtf(rvar[HH + t] + EPSF);
        float sh = beta[HH + t] - rmean[HH + t] * sc;
        sA[t] = sc;
        sB[t] = fmaf(bcp[HH + t], sc, sh);
    }
    __syncthreads();

    int tid = blockIdx.x * 256 + t;   // grid covers NN*8
    int n = tid >> 3;
    int p = tid & 7;
    int nl = t >> 3;
    const float4* hp = (const float4*)g_hb;

    int beg = __ldg(&g_rowstart[n]);
    int end = __ldg(&g_rowstart[n + 1]);

    float4 selfv = __ldg(hp + (size_t)n * 8 + p);   // load early, add last

    float4 acc = make_float4(0.f, 0.f, 0.f, 0.f);
    int r = beg;
    while (r + 8 <= end) {
        int idx[8];
#pragma unroll
        for (int j = 0; j < 8; j++) idx[j] = __ldcs(&g_csrsrc[r + j]);
        float4 hv[8];
#pragma unroll
        for (int j = 0; j < 8; j++) hv[j] = __ldg(hp + (size_t)idx[j] * 8 + p);
        acc = add4(acc, add4(add4(add4(hv[0], hv[1]), add4(hv[2], hv[3])),
                             add4(add4(hv[4], hv[5]), add4(hv[6], hv[7]))));
        r += 8;
    }
    {   // tail m in [0,7]
        int m = end - r;
        int idx[7]; float4 hv[7];
#pragma unroll
        for (int j = 0; j < 7; j++) if (j < m) idx[j] = __ldcs(&g_csrsrc[r + j]);
#pragma unroll
        for (int j = 0; j < 7; j++)
            if (j < m) hv[j] = __ldg(hp + (size_t)idx[j] * 8 + p);
        int s0 = 0;
        if (m >= 4) {
            acc = add4(acc, add4(add4(hv[0], hv[1]), add4(hv[2], hv[3])));
            s0 = 4;
        }
#pragma unroll
        for (int j = 0; j < 7; j++)
            if (j >= s0 && j < m) acc = add4(acc, hv[j]);
    }
    acc = add4(acc, selfv);   // self last

    float dn = g_dinv[n];
    float4 xv;
    xv.x = fmaxf(fmaf(acc.x * dn, sA[4 * p + 0], sB[4 * p + 0]), 0.f);
    xv.y = fmaxf(fmaf(acc.y * dn, sA[4 * p + 1], sB[4 * p + 1]), 0.f);
    xv.z = fmaxf(fmaf(acc.z * dn, sA[4 * p + 2], sB[4 * p + 2]), 0.f);
    xv.w = fmaxf(fmaf(acc.w * dn, sA[4 * p + 3], sB[4 * p + 3]), 0.f);
    *(float4*)(xs + nl * 40 + 4 * p) = xv;
    __syncwarp();

    float xrf[HH];
    {
        const float4* xrp = (const float4*)(xs + nl * 40);
#pragma unroll
        for (int q = 0; q < 8; q++) {
            float4 v = xrp[q];
            xrf[4 * q + 0] = v.x; xrf[4 * q + 1] = v.y;
            xrf[4 * q + 2] = v.z; xrf[4 * q + 3] = v.w;
        }
    }
    unsigned long long a0 = 0ULL, a1 = 0ULL;
#pragma unroll
    for (int k = 0; k < HH; k++) {
        unsigned long long xkk = pk2(xrf[k], xrf[k]);
        ulonglong2 w = Ws2[k * 8 + p];
        fma2(a0, xkk, w.x);
        fma2(a1, xkk, w.y);
    }
    unsigned long long dn2 = pk2(dn, dn);
    unsigned long long o0 = mul2(a0, dn2);
    unsigned long long o1 = mul2(a1, dn2);
    ((ulonglong2*)(g_ha + (size_t)n * HH))[p] = make_ulonglong2(o0, o1);
    if (p == 7) {
        float lo, hi;
        asm("mov.b64 {%0,%1}, %2;" : "=f"(lo), "=f"(hi) : "l"(o1));
        g_c31[n] = hi;   // channel 31, bit-identical to g_ha[n*32+31]
    }
}

// ---------------- layer 2 keys: scalar gather of channel 31 via sidecar -----
__global__ void __launch_bounds__(256) k_gkey(
    const float* __restrict__ bcp,
    const float* __restrict__ gamma, const float* __restrict__ beta,
    const float* __restrict__ rmean, const float* __restrict__ rvar)
{
    int n = blockIdx.x * 256 + threadIdx.x;   // grid covers NN
    float sc = __ldg(&gamma[2 * HH + 31]) * rsqrtf(__ldg(&rvar[2 * HH + 31]) + EPSF);
    float sh = fmaf(__ldg(&bcp[2 * HH + 31]), sc,
                    __ldg(&beta[2 * HH + 31]) - __ldg(&rmean[2 * HH + 31]) * sc);

    int beg = __ldg(&g_rowstart[n]);
    int end = __ldg(&g_rowstart[n + 1]);

    float selfv = __ldg(&g_c31[n]);   // load early, add last

    float acc = 0.f;
    int r = beg;
    while (r + 8 <= end) {
        int idx[8];
#pragma unroll
        for (int j = 0; j < 8; j++) idx[j] = __ldg(&g_csrsrc[r + j]);
        float hv[8];
#pragma unroll
        for (int j = 0; j < 8; j++) hv[j] = __ldg(&g_c31[idx[j]]);
        acc += (((hv[0] + hv[1]) + (hv[2] + hv[3])) +
                ((hv[4] + hv[5]) + (hv[6] + hv[7])));
        r += 8;
    }
    {   // tail m in [0,7]
        int m = end - r;
        int idx[7]; float hv[7];
#pragma unroll
        for (int j = 0; j < 7; j++) if (j < m) idx[j] = __ldg(&g_csrsrc[r + j]);
#pragma unroll
        for (int j = 0; j < 7; j++) if (j < m) hv[j] = __ldg(&g_c31[idx[j]]);
        int s0 = 0;
        if (m >= 4) {
            acc += ((hv[0] + hv[1]) + (hv[2] + hv[3]));
            s0 = 4;
        }
#pragma unroll
        for (int j = 0; j < 7; j++)
            if (j >= s0 && j < m) acc += hv[j];
    }
    acc += selfv;   // self last

    float v = fmaxf(fmaf(acc * g_dinv[n], sc, sh), 0.f);
    g_key[n] = (v == 0.0f) ? 0u : __float_as_uint(v);
}

// ---------------- SortPool: select top-K node ids per graph -----------------
__global__ void __launch_bounds__(256) k_sortpool() {
    __shared__ unsigned long long keys[CAP];
    int b = blockIdx.x, t = threadIdx.x;

    int start = g_start2[b];
    int cnt = g_start2[b + 1] - start;
    int cc = min(cnt, CAP);
    int size = (cc <= 256) ? 256 : CAP;

    for (int r = t; r < size; r += 256) {
        unsigned long long key = 0xFFFFFFFFFFFFFFFFull;
        if (r < cc) {
            unsigned u = g_key[start + r];
            key = ((unsigned long long)(~u) << 32) | (unsigned)r;
        }
        keys[r] = key;
    }
    __syncthreads();

    if (size == 256) {
        for (int k = 2; k <= 256; k <<= 1) {
            for (int j = k >> 1; j > 0; j >>= 1) {
                int i = t;
                int ixj = i ^ j;
                if (ixj > i) {
                    unsigned long long a = keys[i], c = keys[ixj];
                    bool up = ((i & k) == 0);
                    bool sw = up ? (a > c) : (a < c);
                    if (sw) { keys[i] = c; keys[ixj] = a; }
                }
                __syncthreads();
            }
        }
    } else {
        for (int k = 2; k <= CAP; k <<= 1) {
            for (int j = k >> 1; j > 0; j >>= 1) {
                for (int base = 0; base < CAP; base += 256) {
                    int i = base + t;
                    int ixj = i ^ j;
                    if (ixj > i) {
                        unsigned long long a = keys[i], c = keys[ixj];
                        bool up = ((i & k) == 0);
                        bool sw = up ? (a > c) : (a < c);
                        if (sw) { keys[i] = c; keys[ixj] = a; }
                    }
                }
                __syncthreads();
            }
        }
    }

    int nval = min(cc, KK);
    if (t < KK)
        g_sel[b * KK + t] =
            (t < nval) ? start + (int)(unsigned)(keys[t] & 0xFFFFFFFFu) : -1;
}

// ---------------- layer 2 full gather for SELECTED nodes -> pooled ----------
__global__ void __launch_bounds__(256) k_gsel(
    const float* __restrict__ bcp,
    const float* __restrict__ gamma, const float* __restrict__ beta,
    const float* __restrict__ rmean, const float* __restrict__ rvar)
{
    __shared__ float sA[HH], sB[HH];
    int t = threadIdx.x;
    if (t < HH) {
        float sc = gamma[2 * HH + t] * rsqrtf(rvar[2 * HH + t] + EPSF);
        float sh = beta[2 * HH + t] - rmean[2 * HH + t] * sc;
        sA[t] = sc;
        sB[t] = fmaf(bcp[2 * HH + t], sc, sh);
    }
    __syncthreads();

    int tid = blockIdx.x * 256 + t;   // grid covers BB*KK*8
    int slot = tid >> 3;
    int p = tid & 7;
    int n = g_sel[slot];
    float4* outp = (float4*)(g_pooled + (size_t)slot * HH) + p;
    if (n < 0) {
        *outp = make_float4(0.f, 0.f, 0.f, 0.f);
        return;
    }
    const float4* hp = (const float4*)g_ha;

    int beg = __ldg(&g_rowstart[n]);
    int end = __ldg(&g_rowstart[n + 1]);

    float4 selfv = __ldg(hp + (size_t)n * 8 + p);   // load early, add last

    float4 acc = make_float4(0.f, 0.f, 0.f, 0.f);
    int r = beg;
    while (r + 8 <= end) {
        int idx[8];
#pragma unroll
        for (int j = 0; j < 8; j++) idx[j] = __ldg(&g_csrsrc[r + j]);
        float4 hv[8];
#pragma unroll
        for (int j = 0; j < 8; j++) hv[j] = __ldg(hp + (size_t)idx[j] * 8 + p);
        acc = add4(acc, add4(add4(add4(hv[0], hv[1]), add4(hv[2], hv[3])),
                             add4(add4(hv[4], hv[5]), add4(hv[6], hv[7]))));
        r += 8;
    }
    {   // tail m in [0,7]
        int m = end - r;
        int idx[7]; float4 hv[7];
#pragma unroll
        for (int j = 0; j < 7; j++) if (j < m) idx[j] = __ldg(&g_csrsrc[r + j]);
#pragma unroll
        for (int j = 0; j < 7; j++)
            if (j < m) hv[j] = __ldg(hp + (size_t)idx[j] * 8 + p);
        int s0 = 0;
        if (m >= 4) {
            acc = add4(acc, add4(add4(hv[0], hv[1]), add4(hv[2], hv[3])));
            s0 = 4;
        }
#pragma unroll
        for (int j = 0; j < 7; j++)
            if (j >= s0 && j < m) acc = add4(acc, hv[j]);
    }
    acc = add4(acc, selfv);   // self last

    float dn = g_dinv[n];
    float4 xv;
    xv.x = fmaxf(fmaf(acc.x * dn, sA[4 * p + 0], sB[4 * p + 0]), 0.f);
    xv.y = fmaxf(fmaf(acc.y * dn, sA[4 * p + 1], sB[4 * p + 1]), 0.f);
    xv.z = fmaxf(fmaf(acc.z * dn, sA[4 * p + 2], sB[4 * p + 2]), 0.f);
    xv.w = fmaxf(fmaf(acc.w * dn, sA[4 * p + 3], sB[4 * p + 3]), 0.f);
    *outp = xv;
}

// ---------------- MLP head: block-tiled, 32 graphs/block --------------------
__global__ void __launch_bounds__(256) k_mlp(
    const float* __restrict__ W1, const float* __restrict__ b1,
    const float* __restrict__ W2, const float* __restrict__ b2,
    const float* __restrict__ W3, const float* __restrict__ b3,
    float* __restrict__ out)
{
    __shared__ float  Xs[32][33];
    __shared__ float4 Wt[32][8];
    __shared__ float  H1[32][33];
    int t = threadIdx.x;
    int tg = t >> 3, tj = t & 7;
    int g0 = blockIdx.x * 32;

    float4 accf = __ldg((const float4*)b1 + tj);
    unsigned long long a0 = pk2(accf.x, accf.y);
    unsigned long long a1 = pk2(accf.z, accf.w);

    for (int c = 0; c < 30; c++) {
        int p0 = c * 32;
        __syncthreads();
        float4 xv = __ldg((const float4*)(g_pooled + (size_t)(g0 + tg) * (KK * HH)
                                          + p0 + 4 * tj));
        Xs[tg][4 * tj + 0] = xv.x; Xs[tg][4 * tj + 1] = xv.y;
        Xs[tg][4 * tj + 2] = xv.z; Xs[tg][4 * tj + 3] = xv.w;
        Wt[tg][tj] = __ldg((const float4*)(W1 + (size_t)(p0 + tg) * 32 + 4 * tj));
        __syncthreads();
#pragma unroll
        for (int kk = 0; kk < 32; kk++) {
            float xk = Xs[tg][kk];
            unsigned long long xkk = pk2(xk, xk);
            float4 w = Wt[kk][tj];
            fma2(a0, xkk, pk2(w.x, w.y));
            fma2(a1, xkk, pk2(w.z, w.w));
        }
    }
    float r0, r1, r2, r3;
    asm("mov.b64 {%0,%1}, %2;" : "=f"(r0), "=f"(r1) : "l"(a0));
    asm("mov.b64 {%0,%1}, %2;" : "=f"(r2), "=f"(r3) : "l"(a1));
    H1[tg][4 * tj + 0] = fmaxf(r0, 0.f);
    H1[tg][4 * tj + 1] = fmaxf(r1, 0.f);
    H1[tg][4 * tj + 2] = fmaxf(r2, 0.f);
    H1[tg][4 * tj + 3] = fmaxf(r3, 0.f);
    __syncthreads();

    if (t < 32) {
        int g = t;
        float h2a[16];
#pragma unroll
        for (int m = 0; m < 16; m++) h2a[m] = b2[m];
#pragma unroll
        for (int h = 0; h < 32; h++) {
            float x = H1[g][h];
#pragma unroll
            for (int m = 0; m < 16; m++) h2a[m] = fmaf(x, W2[h * 16 + m], h2a[m]);
        }
        float o = b3[0];
#pragma unroll
        for (int m = 0; m < 16; m++) o = fmaf(fmaxf(h2a[m], 0.f), W3[m], o);
        out[g0 + g] = o;
    }
}

// ---------------- launch -----------------------------------------------------
extern "C" void kernel_launch(void* const* d_in, const int* in_sizes, int n_in,
                              void* d_out, int out_size) {
    const int*   xz    = (const int*)d_in[0];
    const int*   ei    = (const int*)d_in[1];
    const int*   batch = (const int*)d_in[2];
    const float* emb   = (const float*)d_in[3];
    const float* Wc    = (const float*)d_in[4];
    const float* bc    = (const float*)d_in[5];
    const float* gamma = (const float*)d_in[6];
    const float* beta  = (const float*)d_in[7];
    const float* rmean = (const float*)d_in[8];
    const float* rvar  = (const float*)d_in[9];
    const float* W1    = (const float*)d_in[10];
    const float* b1    = (const float*)d_in[11];
    const float* W2    = (const float*)d_in[12];
    const float* b2    = (const float*)d_in[13];
    const float* W3    = (const float*)d_in[14];
    const float* b3    = (const float*)d_in[15];
    float* out = (float*)d_out;

    const int* src = ei;
    const int* dst = ei + EE;

    k_embw    <<<NBLK, 256>>>(emb, Wc);                                   // 1
    k_degb    <<<EE / 256, 256>>>(dst, batch);                            // 2
    k_scanA   <<<NBLK, 256>>>(xz);                                        // 3
    k_scanB   <<<NBLK, 256>>>();                                          // 4
    k_fill    <<<EE / 256, 256>>>(src, dst);                              // 5
    k_sortval <<<NBLK, 256>>>();                                          // 6
    k_gbg0    <<<(NN * 8) / 256, 256>>>(Wc, bc, gamma, beta, rmean, rvar);// 7
    k_gbg     <<<(NN * 8) / 256, 256>>>(Wc, bc, gamma, beta, rmean, rvar);// 8
    k_gkey    <<<NBLK, 256>>>(bc, gamma, beta, rmean, rvar);              // 9
    k_sortpool<<<BB, 256>>>();                                            // 10
    k_gsel    <<<(BB * KK * 8) / 256, 256>>>(bc, gamma, beta, rmean, rvar);// 11
    k_mlp     <<<BB / 32, 256>>>(W1, b1, W2, b2, W3, b3, out);            // 12
}

// round 13
// speedup vs baseline: 1.0438x; 1.0438x over previous
#include <cuda_runtime.h>

#define NN 524288
#define EE 4194304
#define BB 4096
#define HH 32
#define KK 30
#define CAP 512
#define MAXZ1 1001
#define EPSF 1e-5f
#define NBLK 2048          // NN/256

// ---------------- scratch (device globals; no allocation allowed) ----------
__device__ int   g_deg[NN];
__device__ float g_dinv[NN];
__device__ int2  g_pack[NN];              // {xz, dinv bits}
__device__ float g_embw[MAXZ1 * HH];      // emb @ W0   (128KB)
__device__ float g_ha[(size_t)NN * HH];   // layer1 out
__device__ float g_hb[(size_t)NN * HH];   // layer0 out
__device__ float g_c31[NN];               // h' channel 31 sidecar (L2-resident)
__device__ unsigned g_key[NN];
__device__ int   g_rowstart[NN + 1];
__device__ int   g_cursor[NN];
__device__ int   g_csrsrc[EE];
__device__ int   g_bsum[NBLK];
__device__ int   g_start2[BB + 1];
__device__ int   g_sel[BB * KK];
__device__ float g_pooled[(size_t)BB * KK * HH];

__device__ __forceinline__ float4 add4(float4 a, float4 b) {
    return make_float4(a.x + b.x, a.y + b.y, a.z + b.z, a.w + b.w);
}
__device__ __forceinline__ float4 scale4(float4 a, float s) {
    return make_float4(a.x * s, a.y * s, a.z * s, a.w * s);
}
__device__ __forceinline__ unsigned long long pk2(float x, float y) {
    unsigned long long r;
    asm("mov.b64 %0, {%1,%2};" : "=l"(r) : "f"(x), "f"(y));
    return r;
}
__device__ __forceinline__ void fma2(unsigned long long& d, unsigned long long a,
                                     unsigned long long b) {
    asm("fma.rn.f32x2 %0, %1, %2, %0;" : "+l"(d) : "l"(a), "l"(b));
}
__device__ __forceinline__ unsigned long long mul2(unsigned long long a,
                                                   unsigned long long b) {
    unsigned long long r;
    asm("mul.rn.f32x2 %0, %1, %2;" : "=l"(r) : "l"(a), "l"(b));
    return r;
}

// ---------------- embW0 = emb @ Wc[0], fused with g_deg zeroing -------------
__global__ void __launch_bounds__(256) k_embw(
    const float* __restrict__ emb, const float* __restrict__ Wc)
{
    __shared__ float Ws[HH * HH];
    int t = threadIdx.x;
    int b = blockIdx.x;
    g_deg[b * 256 + t] = 0;
    if (b < 126) {
        for (int i = t; i < HH * HH; i += 256) Ws[i] = Wc[i];
        __syncthreads();
        int row = b * 8 + (t >> 5);
        int col = t & 31;
        if (row < MAXZ1) {
            const float* er = emb + (size_t)row * HH;
            float acc = 0.f;
#pragma unroll
            for (int k = 0; k < HH; k++) acc = fmaf(er[k], Ws[k * HH + col], acc);
            g_embw[row * HH + col] = acc;
        }
    }
}

// in-degree histogram, 4 edges/thread
__global__ void k_degb(const int* __restrict__ dst) {
    int i = blockIdx.x * 256 + threadIdx.x;   // grid covers EE/4
    int4 d = ((const int4*)dst)[i];
    atomicAdd(&g_deg[d.x], 1);
    atomicAdd(&g_deg[d.y], 1);
    atomicAdd(&g_deg[d.z], 1);
    atomicAdd(&g_deg[d.w], 1);
}

// scanA: block sums of deg + dinv + pack{xz,dinv} + graph boundaries
__global__ void k_scanA(const int* __restrict__ xz, const int* __restrict__ batch) {
    __shared__ int s[256];
    int t = threadIdx.x;
    int i = blockIdx.x * 256 + t;
    int d = g_deg[i];
    float dn = rsqrtf((float)d + 1.0f);
    g_dinv[i] = dn;
    g_pack[i] = make_int2(xz[i], __float_as_int(dn));
    {
        int b1 = batch[i];
        int b0 = (i > 0) ? batch[i - 1] : -1;
        for (int b = b0 + 1; b <= b1; b++) g_start2[b] = i;
        if (i == NN - 1)
            for (int b = b1 + 1; b <= BB; b++) g_start2[b] = NN;
    }
    s[t] = d;
    __syncthreads();
    for (int off = 128; off; off >>= 1) {
        if (t < off) s[t] += s[t + off];
        __syncthreads();
    }
    if (t == 0) g_bsum[blockIdx.x] = s[0];
}

// scanB: each block sums its bsum prefix directly, then local scan
__global__ void __launch_bounds__(256) k_scanB() {
    __shared__ int red[256];
    __shared__ int s[256];
    int b = blockIdx.x, t = threadIdx.x;
    int part = 0;
    for (int j = t; j < b; j += 256) part += g_bsum[j];
    red[t] = part;
    __syncthreads();
    for (int off = 128; off; off >>= 1) {
        if (t < off) red[t] += red[t + off];
        __syncthreads();
    }
    int base = red[0];
    int i = b * 256 + t;
    int d = g_deg[i];
    s[t] = d;
    __syncthreads();
    for (int off = 1; off < 256; off <<= 1) {
        int v = (t >= off) ? s[t - off] : 0;
        __syncthreads();
        s[t] += v;
        __syncthreads();
    }
    int excl = base + s[t] - d;
    g_rowstart[i] = excl;
    g_cursor[i] = excl;
    if (i == NN - 1) g_rowstart[NN] = EE;
}

// ---------------- CSR fill: 4 edges/thread ----------------------------------
__global__ void k_fill(const int* __restrict__ src, const int* __restrict__ dst) {
    int i = blockIdx.x * 256 + threadIdx.x;   // grid covers EE/4
    int4 sv = ((const int4*)src)[i];
    int4 dv = ((const int4*)dst)[i];
    g_csrsrc[atomicAdd(&g_cursor[dv.x], 1)] = sv.x;
    g_csrsrc[atomicAdd(&g_cursor[dv.y], 1)] = sv.y;
    g_csrsrc[atomicAdd(&g_cursor[dv.z], 1)] = sv.z;
    g_csrsrc[atomicAdd(&g_cursor[dv.w], 1)] = sv.w;
}

// ---------------- canonicalize rows: sort src values ascending --------------
__global__ void __launch_bounds__(256) k_sortval() {
    int n = blockIdx.x * 256 + threadIdx.x;
    int beg = g_rowstart[n];
    int len = g_rowstart[n + 1] - beg;
    if (len <= 1) return;
    if (len <= 16) {
        int v[16];
#pragma unroll
        for (int i = 0; i < 16; i++)
            v[i] = (i < len) ? g_csrsrc[beg + i] : 0x7FFFFFFF;
#pragma unroll
        for (int k = 2; k <= 16; k <<= 1) {
#pragma unroll
            for (int j = k >> 1; j > 0; j >>= 1) {
#pragma unroll
                for (int i = 0; i < 16; i++) {
                    int ix = i ^ j;
                    if (ix > i) {
                        bool up = ((i & k) == 0);
                        int a = v[i], c = v[ix];
                        bool sw = up ? (a > c) : (a < c);
                        if (sw) { v[i] = c; v[ix] = a; }
                    }
                }
            }
        }
        for (int i = 0; i < len; i++) g_csrsrc[beg + i] = v[i];
    } else {
        int end = beg + len;
        for (int i = beg + 1; i < end; i++) {
            int key = g_csrsrc[i];
            int j = i - 1;
            while (j >= beg && g_csrsrc[j] > key) {
                g_csrsrc[j + 1] = g_csrsrc[j];
                j--;
            }
            g_csrsrc[j + 1] = key;
        }
    }
}

// ---------------- layer 0 fused: table-gather + BN0 + ReLU + GEMM1 ----------
// 8 thr/node; warp-local sync; GEMM reads activations directly from smem.
__global__ void __launch_bounds__(256) k_gbg0(
    const float* __restrict__ Wc, const float* __restrict__ bcp,
    const float* __restrict__ gamma, const float* __restrict__ beta,
    const float* __restrict__ rmean, const float* __restrict__ rvar)
{
    __shared__ ulonglong2 Ws2[HH * 8];
    __shared__ float sA[HH], sB[HH];
    __shared__ float xs[32 * 40];
    int t = threadIdx.x;
    if (t < HH * 8) Ws2[t] = ((const ulonglong2*)(Wc + 1 * HH * HH))[t];
    if (t < HH) {
        float sc = gamma[t] * rsqrtf(rvar[t] + EPSF);
        float sh = beta[t] - rmean[t] * sc;
        sA[t] = sc;
        sB[t] = fmaf(bcp[t], sc, sh);
    }
    __syncthreads();

    int tid = blockIdx.x * 256 + t;   // grid covers NN*8
    int n = tid >> 3;
    int p = tid & 7;
    int nl = t >> 3;
    const float4* ew = (const float4*)g_embw;

    int beg = __ldg(&g_rowstart[n]);
    int end = __ldg(&g_rowstart[n + 1]);

    float4 acc = make_float4(0.f, 0.f, 0.f, 0.f);
    int r = beg;
    while (r + 8 <= end) {
        int idx[8];
#pragma unroll
        for (int j = 0; j < 8; j++) idx[j] = __ldcs(&g_csrsrc[r + j]);
        int2 pk[8];
#pragma unroll
        for (int j = 0; j < 8; j++) pk[j] = __ldg(&g_pack[idx[j]]);
        float4 hv[8];
#pragma unroll
        for (int j = 0; j < 8; j++)
            hv[j] = scale4(__ldg(ew + (size_t)pk[j].x * 8 + p),
                           __int_as_float(pk[j].y));
        acc = add4(acc, add4(add4(add4(hv[0], hv[1]), add4(hv[2], hv[3])),
                             add4(add4(hv[4], hv[5]), add4(hv[6], hv[7]))));
        r += 8;
    }
    if (r + 4 <= end) {
        int idx[4];
#pragma unroll
        for (int j = 0; j < 4; j++) idx[j] = __ldcs(&g_csrsrc[r + j]);
        int2 pk[4];
#pragma unroll
        for (int j = 0; j < 4; j++) pk[j] = __ldg(&g_pack[idx[j]]);
        float4 hv[4];
#pragma unroll
        for (int j = 0; j < 4; j++)
            hv[j] = scale4(__ldg(ew + (size_t)pk[j].x * 8 + p),
                           __int_as_float(pk[j].y));
        acc = add4(acc, add4(add4(hv[0], hv[1]), add4(hv[2], hv[3])));
        r += 4;
    }
    for (; r < end; r++) {
        int s = __ldcs(&g_csrsrc[r]);
        int2 pk = __ldg(&g_pack[s]);
        acc = add4(acc, scale4(__ldg(ew + (size_t)pk.x * 8 + p),
                               __int_as_float(pk.y)));
    }
    // self term last (matches reference order)
    int2 pks = __ldg(&g_pack[n]);
    float dn = __int_as_float(pks.y);
    acc = add4(acc, scale4(__ldg(ew + (size_t)pks.x * 8 + p), dn));

    float4 xv;
    xv.x = fmaxf(fmaf(acc.x * dn, sA[4 * p + 0], sB[4 * p + 0]), 0.f);
    xv.y = fmaxf(fmaf(acc.y * dn, sA[4 * p + 1], sB[4 * p + 1]), 0.f);
    xv.z = fmaxf(fmaf(acc.z * dn, sA[4 * p + 2], sB[4 * p + 2]), 0.f);
    xv.w = fmaxf(fmaf(acc.w * dn, sA[4 * p + 3], sB[4 * p + 3]), 0.f);
    *(float4*)(xs + nl * 40 + 4 * p) = xv;
    __syncwarp();   // exchange partners are within this warp only

    const float* xrow = xs + nl * 40;
    unsigned long long a0 = 0ULL, a1 = 0ULL;
#pragma unroll
    for (int k = 0; k < HH; k++) {
        float xk = xrow[k];                  // scalar LDS, conflict-free
        unsigned long long xkk = pk2(xk, xk);
        ulonglong2 w = Ws2[k * 8 + p];
        fma2(a0, xkk, w.x);
        fma2(a1, xkk, w.y);
    }
    unsigned long long dn2 = pk2(dn, dn);
    ((ulonglong2*)(g_hb + (size_t)n * HH))[p] =
        make_ulonglong2(mul2(a0, dn2), mul2(a1, dn2));
}

// ---------------- layer 1 fused: gather(hb) + BN1 + ReLU + GEMM2 -> ha ------
// Also writes channel-31 sidecar g_c31 (bit-identical value).
__global__ void __launch_bounds__(256) k_gbg(
    const float* __restrict__ Wc, const float* __restrict__ bcp,
    const float* __restrict__ gamma, const float* __restrict__ beta,
    const float* __restrict__ rmean, const float* __restrict__ rvar)
{
    __shared__ ulonglong2 Ws2[HH * 8];
    __shared__ float sA[HH], sB[HH];
    __shared__ float xs[32 * 40];
    int t = threadIdx.x;
    if (t < HH * 8) Ws2[t] = ((const ulonglong2*)(Wc + 2 * HH * HH))[t];
    if (t < HH) {
        float sc = gamma[HH + t] * rsqrtf(rvar[HH + t] + EPSF);
        float sh = beta[HH + t] - rmean[HH + t] * sc;
        sA[t] = sc;
        sB[t] = fmaf(bcp[HH + t], sc, sh);
    }
    __syncthreads();

    int tid = blockIdx.x * 256 + t;   // grid covers NN*8
    int n = tid >> 3;
    int p = tid & 7;
    int nl = t >> 3;
    const float4* hp = (const float4*)g_hb;

    int beg = __ldg(&g_rowstart[n]);
    int end = __ldg(&g_rowstart[n + 1]);

    float4 acc = make_float4(0.f, 0.f, 0.f, 0.f);
    int r = beg;
    while (r + 8 <= end) {
        int idx[8];
#pragma unroll
        for (int j = 0; j < 8; j++) idx[j] = __ldcs(&g_csrsrc[r + j]);
        float4 hv[8];
#pragma unroll
        for (int j = 0; j < 8; j++) hv[j] = __ldg(hp + (size_t)idx[j] * 8 + p);
        acc = add4(acc, add4(add4(add4(hv[0], hv[1]), add4(hv[2], hv[3])),
                             add4(add4(hv[4], hv[5]), add4(hv[6], hv[7]))));
        r += 8;
    }
    if (r + 4 <= end) {
        int idx[4];
#pragma unroll
        for (int j = 0; j < 4; j++) idx[j] = __ldcs(&g_csrsrc[r + j]);
        float4 hv[4];
#pragma unroll
        for (int j = 0; j < 4; j++) hv[j] = __ldg(hp + (size_t)idx[j] * 8 + p);
        acc = add4(acc, add4(add4(hv[0], hv[1]), add4(hv[2], hv[3])));
        r += 4;
    }
    for (; r < end; r++) {
        int s = __ldcs(&g_csrsrc[r]);
        acc = add4(acc, __ldg(hp + (size_t)s * 8 + p));
    }
    acc = add4(acc, __ldg(hp + (size_t)n * 8 + p));   // self last

    float dn = g_dinv[n];
    float4 xv;
    xv.x = fmaxf(fmaf(acc.x * dn, sA[4 * p + 0], sB[4 * p + 0]), 0.f);
    xv.y = fmaxf(fmaf(acc.y * dn, sA[4 * p + 1], sB[4 * p + 1]), 0.f);
    xv.z = fmaxf(fmaf(acc.z * dn, sA[4 * p + 2], sB[4 * p + 2]), 0.f);
    xv.w = fmaxf(fmaf(acc.w * dn, sA[4 * p + 3], sB[4 * p + 3]), 0.f);
    *(float4*)(xs + nl * 40 + 4 * p) = xv;
    __syncwarp();   // exchange partners are within this warp only

    const float* xrow = xs + nl * 40;
    unsigned long long a0 = 0ULL, a1 = 0ULL;
#pragma unroll
    for (int k = 0; k < HH; k++) {
        float xk = xrow[k];                  // scalar LDS, conflict-free
        unsigned long long xkk = pk2(xk, xk);
        ulonglong2 w = Ws2[k * 8 + p];
        fma2(a0, xkk, w.x);
        fma2(a1, xkk, w.y);
    }
    unsigned long long dn2 = pk2(dn, dn);
    unsigned long long o0 = mul2(a0, dn2);
    unsigned long long o1 = mul2(a1, dn2);
    ((ulonglong2*)(g_ha + (size_t)n * HH))[p] = make_ulonglong2(o0, o1);
    if (p == 7) {
        float lo, hi;
        asm("mov.b64 {%0,%1}, %2;" : "=f"(lo), "=f"(hi) : "l"(o1));
        g_c31[n] = hi;   // channel 31, bit-identical to g_ha[n*32+31]
    }
}

// ---------------- layer 2 keys: scalar gather of channel 31 via sidecar -----
__global__ void __launch_bounds__(256) k_gkey(
    const float* __restrict__ bcp,
    const float* __restrict__ gamma, const float* __restrict__ beta,
    const float* __restrict__ rmean, const float* __restrict__ rvar)
{
    int n = blockIdx.x * 256 + threadIdx.x;   // grid covers NN
    float sc = __ldg(&gamma[2 * HH + 31]) * rsqrtf(__ldg(&rvar[2 * HH + 31]) + EPSF);
    float sh = fmaf(__ldg(&bcp[2 * HH + 31]), sc,
                    __ldg(&beta[2 * HH + 31]) - __ldg(&rmean[2 * HH + 31]) * sc);

    int beg = __ldg(&g_rowstart[n]);
    int end = __ldg(&g_rowstart[n + 1]);

    float acc = 0.f;
    int r = beg;
    while (r + 8 <= end) {
        int idx[8];
#pragma unroll
        for (int j = 0; j < 8; j++) idx[j] = __ldg(&g_csrsrc[r + j]);
        float hv[8];
#pragma unroll
        for (int j = 0; j < 8; j++) hv[j] = __ldg(&g_c31[idx[j]]);
        acc += (((hv[0] + hv[1]) + (hv[2] + hv[3])) +
                ((hv[4] + hv[5]) + (hv[6] + hv[7])));
        r += 8;
    }
    if (r + 4 <= end) {
        int idx[4];
#pragma unroll
        for (int j = 0; j < 4; j++) idx[j] = __ldg(&g_csrsrc[r + j]);
        float hv[4];
#pragma unroll
        for (int j = 0; j < 4; j++) hv[j] = __ldg(&g_c31[idx[j]]);
        acc += ((hv[0] + hv[1]) + (hv[2] + hv[3]));
        r += 4;
    }
    for (; r < end; r++)
        acc += __ldg(&g_c31[__ldg(&g_csrsrc[r])]);
    acc += __ldg(&g_c31[n]);   // self last

    float v = fmaxf(fmaf(acc * g_dinv[n], sc, sh), 0.f);
    g_key[n] = (v == 0.0f) ? 0u : __float_as_uint(v);
}

// ---------------- SortPool: select top-K node ids per graph -----------------
__global__ void __launch_bounds__(256) k_sortpool() {
    __shared__ unsigned long long keys[CAP];
    int b = blockIdx.x, t = threadIdx.x;

    int start = g_start2[b];
    int cnt = g_start2[b + 1] - start;
    int cc = min(cnt, CAP);
    int size = (cc <= 256) ? 256 : CAP;

    for (int r = t; r < size; r += 256) {
        unsigned long long key = 0xFFFFFFFFFFFFFFFFull;
        if (r < cc) {
            unsigned u = g_key[start + r];
            key = ((unsigned long long)(~u) << 32) | (unsigned)r;
        }
        keys[r] = key;
    }
    __syncthreads();

    if (size == 256) {
        for (int k = 2; k <= 256; k <<= 1) {
            for (int j = k >> 1; j > 0; j >>= 1) {
                int i = t;
                int ixj = i ^ j;
                if (ixj > i) {
                    unsigned long long a = keys[i], c = keys[ixj];
                    bool up = ((i & k) == 0);
                    bool sw = up ? (a > c) : (a < c);
                    if (sw) { keys[i] = c; keys[ixj] = a; }
                }
                __syncthreads();
            }
        }
    } else {
        for (int k = 2; k <= CAP; k <<= 1) {
            for (int j = k >> 1; j > 0; j >>= 1) {
                for (int base = 0; base < CAP; base += 256) {
                    int i = base + t;
                    int ixj = i ^ j;
                    if (ixj > i) {
                        unsigned long long a = keys[i], c = keys[ixj];
                        bool up = ((i & k) == 0);
                        bool sw = up ? (a > c) : (a < c);
                        if (sw) { keys[i] = c; keys[ixj] = a; }
                    }
                }
                __syncthreads();
            }
        }
    }

    int nval = min(cc, KK);
    if (t < KK)
        g_sel[b * KK + t] =
            (t < nval) ? start + (int)(unsigned)(keys[t] & 0xFFFFFFFFu) : -1;
}

// ---------------- layer 2 full gather for SELECTED nodes -> pooled ----------
__global__ void __launch_bounds__(256) k_gsel(
    const float* __restrict__ bcp,
    const float* __restrict__ gamma, const float* __restrict__ beta,
    const float* __restrict__ rmean, const float* __restrict__ rvar)
{
    __shared__ float sA[HH], sB[HH];
    int t = threadIdx.x;
    if (t < HH) {
        float sc = gamma[2 * HH + t] * rsqrtf(rvar[2 * HH + t] + EPSF);
        float sh = beta[2 * HH + t] - rmean[2 * HH + t] * sc;
        sA[t] = sc;
        sB[t] = fmaf(bcp[2 * HH + t], sc, sh);
    }
    __syncthreads();

    int tid = blockIdx.x * 256 + t;   // grid covers BB*KK*8
    int slot = tid >> 3;
    int p = tid & 7;
    int n = g_sel[slot];
    float4* outp = (float4*)(g_pooled + (size_t)slot * HH) + p;
    if (n < 0) {
        *outp = make_float4(0.f, 0.f, 0.f, 0.f);
        return;
    }
    const float4* hp = (const float4*)g_ha;

    int beg = __ldg(&g_rowstart[n]);
    int end = __ldg(&g_rowstart[n + 1]);

    float4 acc = make_float4(0.f, 0.f, 0.f, 0.f);
    int r = beg;
    while (r + 8 <= end) {
        int idx[8];
#pragma unroll
        for (int j = 0; j < 8; j++) idx[j] = __ldg(&g_csrsrc[r + j]);
        float4 hv[8];
#pragma unroll
        for (int j = 0; j < 8; j++) hv[j] = __ldg(hp + (size_t)idx[j] * 8 + p);
        acc = add4(acc, add4(add4(add4(hv[0], hv[1]), add4(hv[2], hv[3])),
                             add4(add4(hv[4], hv[5]), add4(hv[6], hv[7]))));
        r += 8;
    }
    if (r + 4 <= end) {
        int idx[4];
#pragma unroll
        for (int j = 0; j < 4; j++) idx[j] = __ldg(&g_csrsrc[r + j]);
        float4 hv[4];
#pragma unroll
        for (int j = 0; j < 4; j++) hv[j] = __ldg(hp + (size_t)idx[j] * 8 + p);
        acc = add4(acc, add4(add4(hv[0], hv[1]), add4(hv[2], hv[3])));
        r += 4;
    }
    for (; r < end; r++) {
        int s = __ldg(&g_csrsrc[r]);
        acc = add4(acc, __ldg(hp + (size_t)s * 8 + p));
    }
    acc = add4(acc, __ldg(hp + (size_t)n * 8 + p));   // self last

    float dn = g_dinv[n];
    float4 xv;
    xv.x = fmaxf(fmaf(acc.x * dn, sA[4 * p + 0], sB[4 * p + 0]), 0.f);
    xv.y = fmaxf(fmaf(acc.y * dn, sA[4 * p + 1], sB[4 * p + 1]), 0.f);
    xv.z = fmaxf(fmaf(acc.z * dn, sA[4 * p + 2], sB[4 * p + 2]), 0.f);
    xv.w = fmaxf(fmaf(acc.w * dn, sA[4 * p + 3], sB[4 * p + 3]), 0.f);
    *outp = xv;
}

// ---------------- MLP head: block-tiled, 32 graphs/block --------------------
__global__ void __launch_bounds__(256) k_mlp(
    const float* __restrict__ W1, const float* __restrict__ b1,
    const float* __restrict__ W2, const float* __restrict__ b2,
    const float* __restrict__ W3, const float* __restrict__ b3,
    float* __restrict__ out)
{
    __shared__ float  Xs[32][33];
    __shared__ float4 Wt[32][8];
    __shared__ float  H1[32][33];
    int t = threadIdx.x;
    int tg = t >> 3, tj = t & 7;
    int g0 = blockIdx.x * 32;

    float4 accf = __ldg((const float4*)b1 + tj);
    unsigned long long a0 = pk2(accf.x, accf.y);
    unsigned long long a1 = pk2(accf.z, accf.w);

    for (int c = 0; c < 30; c++) {
        int p0 = c * 32;
        __syncthreads();
        float4 xv = __ldg((const float4*)(g_pooled + (size_t)(g0 + tg) * (KK * HH)
                                          + p0 + 4 * tj));
        Xs[tg][4 * tj + 0] = xv.x; Xs[tg][4 * tj + 1] = xv.y;
        Xs[tg][4 * tj + 2] = xv.z; Xs[tg][4 * tj + 3] = xv.w;
        Wt[tg][tj] = __ldg((const float4*)(W1 + (size_t)(p0 + tg) * 32 + 4 * tj));
        __syncthreads();
#pragma unroll
        for (int kk = 0; kk < 32; kk++) {
            float xk = Xs[tg][kk];
            unsigned long long xkk = pk2(xk, xk);
            float4 w = Wt[kk][tj];
            fma2(a0, xkk, pk2(w.x, w.y));
            fma2(a1, xkk, pk2(w.z, w.w));
        }
    }
    float r0, r1, r2, r3;
    asm("mov.b64 {%0,%1}, %2;" : "=f"(r0), "=f"(r1) : "l"(a0));
    asm("mov.b64 {%0,%1}, %2;" : "=f"(r2), "=f"(r3) : "l"(a1));
    H1[tg][4 * tj + 0] = fmaxf(r0, 0.f);
    H1[tg][4 * tj + 1] = fmaxf(r1, 0.f);
    H1[tg][4 * tj + 2] = fmaxf(r2, 0.f);
    H1[tg][4 * tj + 3] = fmaxf(r3, 0.f);
    __syncthreads();

    if (t < 32) {
        int g = t;
        float h2a[16];
#pragma unroll
        for (int m = 0; m < 16; m++) h2a[m] = b2[m];
#pragma unroll
        for (int h = 0; h < 32; h++) {
            float x = H1[g][h];
#pragma unroll
            for (int m = 0; m < 16; m++) h2a[m] = fmaf(x, W2[h * 16 + m], h2a[m]);
        }
        float o = b3[0];
#pragma unroll
        for (int m = 0; m < 16; m++) o = fmaf(fmaxf(h2a[m], 0.f), W3[m], o);
        out[g0 + g] = o;
    }
}

// ---------------- launch -----------------------------------------------------
extern "C" void kernel_launch(void* const* d_in, const int* in_sizes, int n_in,
                              void* d_out, int out_size) {
    const int*   xz    = (const int*)d_in[0];
    const int*   ei    = (const int*)d_in[1];
    const int*   batch = (const int*)d_in[2];
    const float* emb   = (const float*)d_in[3];
    const float* Wc    = (const float*)d_in[4];
    const float* bc    = (const float*)d_in[5];
    const float* gamma = (const float*)d_in[6];
    const float* beta  = (const float*)d_in[7];
    const float* rmean = (const float*)d_in[8];
    const float* rvar  = (const float*)d_in[9];
    const float* W1    = (const float*)d_in[10];
    const float* b1    = (const float*)d_in[11];
    const float* W2    = (const float*)d_in[12];
    const float* b2    = (const float*)d_in[13];
    const float* W3    = (const float*)d_in[14];
    const float* b3    = (const float*)d_in[15];
    float* out = (float*)d_out;

    const int* src = ei;
    const int* dst = ei + EE;

    k_embw    <<<NBLK, 256>>>(emb, Wc);                                   // 1
    k_degb    <<<EE / 1024, 256>>>(dst);                                  // 2
    k_scanA   <<<NBLK, 256>>>(xz, batch);                                 // 3
    k_scanB   <<<NBLK, 256>>>();                                          // 4
    k_fill    <<<EE / 1024, 256>>>(src, dst);                             // 5
    k_sortval <<<NBLK, 256>>>();                                          // 6
    k_gbg0    <<<(NN * 8) / 256, 256>>>(Wc, bc, gamma, beta, rmean, rvar);// 7
    k_gbg     <<<(NN * 8) / 256, 256>>>(Wc, bc, gamma, beta, rmean, rvar);// 8
    k_gkey    <<<NBLK, 256>>>(bc, gamma, beta, rmean, rvar);              // 9
    k_sortpool<<<BB, 256>>>();                                            // 10
    k_gsel    <<<(BB * KK * 8) / 256, 256>>>(bc, gamma, beta, rmean, rvar);// 11
    k_mlp     <<<BB / 32, 256>>>(W1, b1, W2, b2, W3, b3, out);            // 12
}

// round 14
// speedup vs baseline: 1.0657x; 1.0209x over previous
#include <cuda_runtime.h>

#define NN 524288
#define EE 4194304
#define BB 4096
#define HH 32
#define KK 30
#define CAP 512
#define MAXZ1 1001
#define EPSF 1e-5f
#define NBLK 2048          // NN/256

// ---------------- scratch (device globals; no allocation allowed) ----------
__device__ int   g_deg[NN];
__device__ float g_dinv[NN];
__device__ int2  g_pack[NN];              // {xz, dinv bits}
__device__ float g_embw[MAXZ1 * HH];      // emb @ W0   (128KB)
__device__ float g_ha[(size_t)NN * HH];   // layer1 out
__device__ float g_hb[(size_t)NN * HH];   // layer0 out
__device__ float g_c31[NN];               // h' channel 31 sidecar (L2-resident)
__device__ int   g_rowstart[NN + 1];
__device__ int   g_cursor[NN];
__device__ int   g_csrsrc[EE];
__device__ int   g_bsum[NBLK];
__device__ int   g_start2[BB + 1];
__device__ float g_pooled[(size_t)BB * KK * HH];

__device__ __forceinline__ float4 add4(float4 a, float4 b) {
    return make_float4(a.x + b.x, a.y + b.y, a.z + b.z, a.w + b.w);
}
__device__ __forceinline__ float4 scale4(float4 a, float s) {
    return make_float4(a.x * s, a.y * s, a.z * s, a.w * s);
}
__device__ __forceinline__ unsigned long long pk2(float x, float y) {
    unsigned long long r;
    asm("mov.b64 %0, {%1,%2};" : "=l"(r) : "f"(x), "f"(y));
    return r;
}
__device__ __forceinline__ void fma2(unsigned long long& d, unsigned long long a,
                                     unsigned long long b) {
    asm("fma.rn.f32x2 %0, %1, %2, %0;" : "+l"(d) : "l"(a), "l"(b));
}
__device__ __forceinline__ unsigned long long mul2(unsigned long long a,
                                                   unsigned long long b) {
    unsigned long long r;
    asm("mul.rn.f32x2 %0, %1, %2;" : "=l"(r) : "l"(a), "l"(b));
    return r;
}

// ---------------- embW0 = emb @ Wc[0], fused with g_deg zeroing -------------
__global__ void __launch_bounds__(256) k_embw(
    const float* __restrict__ emb, const float* __restrict__ Wc)
{
    __shared__ float Ws[HH * HH];
    int t = threadIdx.x;
    int b = blockIdx.x;
    g_deg[b * 256 + t] = 0;
    if (b < 126) {
        for (int i = t; i < HH * HH; i += 256) Ws[i] = Wc[i];
        __syncthreads();
        int row = b * 8 + (t >> 5);
        int col = t & 31;
        if (row < MAXZ1) {
            const float* er = emb + (size_t)row * HH;
            float acc = 0.f;
#pragma unroll
            for (int k = 0; k < HH; k++) acc = fmaf(er[k], Ws[k * HH + col], acc);
            g_embw[row * HH + col] = acc;
        }
    }
}

// in-degree histogram, 4 edges/thread
__global__ void k_degb(const int* __restrict__ dst) {
    int i = blockIdx.x * 256 + threadIdx.x;   // grid covers EE/4
    int4 d = ((const int4*)dst)[i];
    atomicAdd(&g_deg[d.x], 1);
    atomicAdd(&g_deg[d.y], 1);
    atomicAdd(&g_deg[d.z], 1);
    atomicAdd(&g_deg[d.w], 1);
}

// scanA: block sums of deg + dinv + pack{xz,dinv} + graph boundaries
__global__ void k_scanA(const int* __restrict__ xz, const int* __restrict__ batch) {
    __shared__ int s[256];
    int t = threadIdx.x;
    int i = blockIdx.x * 256 + t;
    int d = g_deg[i];
    float dn = rsqrtf((float)d + 1.0f);
    g_dinv[i] = dn;
    g_pack[i] = make_int2(xz[i], __float_as_int(dn));
    {
        int b1 = batch[i];
        int b0 = (i > 0) ? batch[i - 1] : -1;
        for (int b = b0 + 1; b <= b1; b++) g_start2[b] = i;
        if (i == NN - 1)
            for (int b = b1 + 1; b <= BB; b++) g_start2[b] = NN;
    }
    s[t] = d;
    __syncthreads();
    for (int off = 128; off; off >>= 1) {
        if (t < off) s[t] += s[t + off];
        __syncthreads();
    }
    if (t == 0) g_bsum[blockIdx.x] = s[0];
}

// scanB: each block sums its bsum prefix directly, then local scan
__global__ void __launch_bounds__(256) k_scanB() {
    __shared__ int red[256];
    __shared__ int s[256];
    int b = blockIdx.x, t = threadIdx.x;
    int part = 0;
    for (int j = t; j < b; j += 256) part += g_bsum[j];
    red[t] = part;
    __syncthreads();
    for (int off = 128; off; off >>= 1) {
        if (t < off) red[t] += red[t + off];
        __syncthreads();
    }
    int base = red[0];
    int i = b * 256 + t;
    int d = g_deg[i];
    s[t] = d;
    __syncthreads();
    for (int off = 1; off < 256; off <<= 1) {
        int v = (t >= off) ? s[t - off] : 0;
        __syncthreads();
        s[t] += v;
        __syncthreads();
    }
    int excl = base + s[t] - d;
    g_rowstart[i] = excl;
    g_cursor[i] = excl;
    if (i == NN - 1) g_rowstart[NN] = EE;
}

// ---------------- CSR fill: 4 edges/thread ----------------------------------
__global__ void k_fill(const int* __restrict__ src, const int* __restrict__ dst) {
    int i = blockIdx.x * 256 + threadIdx.x;   // grid covers EE/4
    int4 sv = ((const int4*)src)[i];
    int4 dv = ((const int4*)dst)[i];
    g_csrsrc[atomicAdd(&g_cursor[dv.x], 1)] = sv.x;
    g_csrsrc[atomicAdd(&g_cursor[dv.y], 1)] = sv.y;
    g_csrsrc[atomicAdd(&g_cursor[dv.z], 1)] = sv.z;
    g_csrsrc[atomicAdd(&g_cursor[dv.w], 1)] = sv.w;
}

// ---------------- canonicalize rows: sort src values ascending --------------
__global__ void __launch_bounds__(256) k_sortval() {
    int n = blockIdx.x * 256 + threadIdx.x;
    int beg = g_rowstart[n];
    int len = g_rowstart[n + 1] - beg;
    if (len <= 1) return;
    if (len <= 16) {
        int v[16];
#pragma unroll
        for (int i = 0; i < 16; i++)
            v[i] = (i < len) ? g_csrsrc[beg + i] : 0x7FFFFFFF;
#pragma unroll
        for (int k = 2; k <= 16; k <<= 1) {
#pragma unroll
            for (int j = k >> 1; j > 0; j >>= 1) {
#pragma unroll
                for (int i = 0; i < 16; i++) {
                    int ix = i ^ j;
                    if (ix > i) {
                        bool up = ((i & k) == 0);
                        int a = v[i], c = v[ix];
                        bool sw = up ? (a > c) : (a < c);
                        if (sw) { v[i] = c; v[ix] = a; }
                    }
                }
            }
        }
        for (int i = 0; i < len; i++) g_csrsrc[beg + i] = v[i];
    } else {
        int end = beg + len;
        for (int i = beg + 1; i < end; i++) {
            int key = g_csrsrc[i];
            int j = i - 1;
            while (j >= beg && g_csrsrc[j] > key) {
                g_csrsrc[j + 1] = g_csrsrc[j];
                j--;
            }
            g_csrsrc[j + 1] = key;
        }
    }
}

// ---------------- layer 0 fused: table-gather + BN0 + ReLU + GEMM1 ----------
__global__ void __launch_bounds__(256) k_gbg0(
    const float* __restrict__ Wc, const float* __restrict__ bcp,
    const float* __restrict__ gamma, const float* __restrict__ beta,
    const float* __restrict__ rmean, const float* __restrict__ rvar)
{
    __shared__ ulonglong2 Ws2[HH * 8];
    __shared__ float sA[HH], sB[HH];
    __shared__ float xs[32 * 40];
    int t = threadIdx.x;
    if (t < HH * 8) Ws2[t] = ((const ulonglong2*)(Wc + 1 * HH * HH))[t];
    if (t < HH) {
        float sc = gamma[t] * rsqrtf(rvar[t] + EPSF);
        float sh = beta[t] - rmean[t] * sc;
        sA[t] = sc;
        sB[t] = fmaf(bcp[t], sc, sh);
    }
    __syncthreads();

    int tid = blockIdx.x * 256 + t;   // grid covers NN*8
    int n = tid >> 3;
    int p = tid & 7;
    int nl = t >> 3;
    const float4* ew = (const float4*)g_embw;

    int beg = __ldg(&g_rowstart[n]);
    int end = __ldg(&g_rowstart[n + 1]);

    float4 acc = make_float4(0.f, 0.f, 0.f, 0.f);
    int r = beg;
    while (r + 8 <= end) {
        int idx[8];
#pragma unroll
        for (int j = 0; j < 8; j++) idx[j] = __ldcs(&g_csrsrc[r + j]);
        int2 pk[8];
#pragma unroll
        for (int j = 0; j < 8; j++) pk[j] = __ldg(&g_pack[idx[j]]);
        float4 hv[8];
#pragma unroll
        for (int j = 0; j < 8; j++)
            hv[j] = scale4(__ldg(ew + (size_t)pk[j].x * 8 + p),
                           __int_as_float(pk[j].y));
        acc = add4(acc, add4(add4(add4(hv[0], hv[1]), add4(hv[2], hv[3])),
                             add4(add4(hv[4], hv[5]), add4(hv[6], hv[7]))));
        r += 8;
    }
    if (r + 4 <= end) {
        int idx[4];
#pragma unroll
        for (int j = 0; j < 4; j++) idx[j] = __ldcs(&g_csrsrc[r + j]);
        int2 pk[4];
#pragma unroll
        for (int j = 0; j < 4; j++) pk[j] = __ldg(&g_pack[idx[j]]);
        float4 hv[4];
#pragma unroll
        for (int j = 0; j < 4; j++)
            hv[j] = scale4(__ldg(ew + (size_t)pk[j].x * 8 + p),
                           __int_as_float(pk[j].y));
        acc = add4(acc, add4(add4(hv[0], hv[1]), add4(hv[2], hv[3])));
        r += 4;
    }
    for (; r < end; r++) {
        int s = __ldcs(&g_csrsrc[r]);
        int2 pk = __ldg(&g_pack[s]);
        acc = add4(acc, scale4(__ldg(ew + (size_t)pk.x * 8 + p),
                               __int_as_float(pk.y)));
    }
    // self term last (matches reference order)
    int2 pks = __ldg(&g_pack[n]);
    float dn = __int_as_float(pks.y);
    acc = add4(acc, scale4(__ldg(ew + (size_t)pks.x * 8 + p), dn));

    float4 xv;
    xv.x = fmaxf(fmaf(acc.x * dn, sA[4 * p + 0], sB[4 * p + 0]), 0.f);
    xv.y = fmaxf(fmaf(acc.y * dn, sA[4 * p + 1], sB[4 * p + 1]), 0.f);
    xv.z = fmaxf(fmaf(acc.z * dn, sA[4 * p + 2], sB[4 * p + 2]), 0.f);
    xv.w = fmaxf(fmaf(acc.w * dn, sA[4 * p + 3], sB[4 * p + 3]), 0.f);
    *(float4*)(xs + nl * 40 + 4 * p) = xv;
    __syncwarp();   // exchange partners are within this warp only

    const float* xrow = xs + nl * 40;
    unsigned long long a0 = 0ULL, a1 = 0ULL;
#pragma unroll
    for (int k = 0; k < HH; k++) {
        float xk = xrow[k];                  // scalar LDS, conflict-free
        unsigned long long xkk = pk2(xk, xk);
        ulonglong2 w = Ws2[k * 8 + p];
        fma2(a0, xkk, w.x);
        fma2(a1, xkk, w.y);
    }
    unsigned long long dn2 = pk2(dn, dn);
    ((ulonglong2*)(g_hb + (size_t)n * HH))[p] =
        make_ulonglong2(mul2(a0, dn2), mul2(a1, dn2));
}

// ---------------- layer 1 fused: gather(hb) + BN1 + ReLU + GEMM2 -> ha ------
// Also writes channel-31 sidecar g_c31 (bit-identical value).
__global__ void __launch_bounds__(256) k_gbg(
    const float* __restrict__ Wc, const float* __restrict__ bcp,
    const float* __restrict__ gamma, const float* __restrict__ beta,
    const float* __restrict__ rmean, const float* __restrict__ rvar)
{
    __shared__ ulonglong2 Ws2[HH * 8];
    __shared__ float sA[HH], sB[HH];
    __shared__ float xs[32 * 40];
    int t = threadIdx.x;
    if (t < HH * 8) Ws2[t] = ((const ulonglong2*)(Wc + 2 * HH * HH))[t];
    if (t < HH) {
        float sc = gamma[HH + t] * rsqrtf(rvar[HH + t] + EPSF);
        float sh = beta[HH + t] - rmean[HH + t] * sc;
        sA[t] = sc;
        sB[t] = fmaf(bcp[HH + t], sc, sh);
    }
    __syncthreads();

    int tid = blockIdx.x * 256 + t;   // grid covers NN*8
    int n = tid >> 3;
    int p = tid & 7;
    int nl = t >> 3;
    const float4* hp = (const float4*)g_hb;

    int beg = __ldg(&g_rowstart[n]);
    int end = __ldg(&g_rowstart[n + 1]);

    float4 acc = make_float4(0.f, 0.f, 0.f, 0.f);
    int r = beg;
    while (r + 8 <= end) {
        int idx[8];
#pragma unroll
        for (int j = 0; j < 8; j++) idx[j] = __ldcs(&g_csrsrc[r + j]);
        float4 hv[8];
#pragma unroll
        for (int j = 0; j < 8; j++) hv[j] = __ldg(hp + (size_t)idx[j] * 8 + p);
        acc = add4(acc, add4(add4(add4(hv[0], hv[1]), add4(hv[2], hv[3])),
                             add4(add4(hv[4], hv[5]), add4(hv[6], hv[7]))));
        r += 8;
    }
    if (r + 4 <= end) {
        int idx[4];
#pragma unroll
        for (int j = 0; j < 4; j++) idx[j] = __ldcs(&g_csrsrc[r + j]);
        float4 hv[4];
#pragma unroll
        for (int j = 0; j < 4; j++) hv[j] = __ldg(hp + (size_t)idx[j] * 8 + p);
        acc = add4(acc, add4(add4(hv[0], hv[1]), add4(hv[2], hv[3])));
        r += 4;
    }
    for (; r < end; r++) {
        int s = __ldcs(&g_csrsrc[r]);
        acc = add4(acc, __ldg(hp + (size_t)s * 8 + p));
    }
    acc = add4(acc, __ldg(hp + (size_t)n * 8 + p));   // self last

    float dn = g_dinv[n];
    float4 xv;
    xv.x = fmaxf(fmaf(acc.x * dn, sA[4 * p + 0], sB[4 * p + 0]), 0.f);
    xv.y = fmaxf(fmaf(acc.y * dn, sA[4 * p + 1], sB[4 * p + 1]), 0.f);
    xv.z = fmaxf(fmaf(acc.z * dn, sA[4 * p + 2], sB[4 * p + 2]), 0.f);
    xv.w = fmaxf(fmaf(acc.w * dn, sA[4 * p + 3], sB[4 * p + 3]), 0.f);
    *(float4*)(xs + nl * 40 + 4 * p) = xv;
    __syncwarp();   // exchange partners are within this warp only

    const float* xrow = xs + nl * 40;
    unsigned long long a0 = 0ULL, a1 = 0ULL;
#pragma unroll
    for (int k = 0; k < HH; k++) {
        float xk = xrow[k];                  // scalar LDS, conflict-free
        unsigned long long xkk = pk2(xk, xk);
        ulonglong2 w = Ws2[k * 8 + p];
        fma2(a0, xkk, w.x);
        fma2(a1, xkk, w.y);
    }
    unsigned long long dn2 = pk2(dn, dn);
    unsigned long long o0 = mul2(a0, dn2);
    unsigned long long o1 = mul2(a1, dn2);
    ((ulonglong2*)(g_ha + (size_t)n * HH))[p] = make_ulonglong2(o0, o1);
    if (p == 7) {
        float lo, hi;
        asm("mov.b64 {%0,%1}, %2;" : "=f"(lo), "=f"(hi) : "l"(o1));
        g_c31[n] = hi;   // channel 31, bit-identical to g_ha[n*32+31]
    }
}

// ---------------- FUSED SortPool: key gather + sort + top-K full gather -----
// One block per graph. Phase 1: per-node channel-31 key (same summation as
// old k_gkey). Phase 2: bitonic sort in smem. Phase 3: full gather for the
// selected <=30 nodes (same summation as old k_gsel) -> g_pooled.
__global__ void __launch_bounds__(256) k_sortpool(
    const float* __restrict__ bcp,
    const float* __restrict__ gamma, const float* __restrict__ beta,
    const float* __restrict__ rmean, const float* __restrict__ rvar)
{
    __shared__ unsigned long long keys[CAP];
    __shared__ int ssel[KK];
    __shared__ float sA[HH], sB[HH];
    int b = blockIdx.x, t = threadIdx.x;
    if (t < HH) {
        float sc = gamma[2 * HH + t] * rsqrtf(rvar[2 * HH + t] + EPSF);
        float sh = beta[2 * HH + t] - rmean[2 * HH + t] * sc;
        sA[t] = sc;
        sB[t] = fmaf(bcp[2 * HH + t], sc, sh);
    }
    __syncthreads();

    int start = g_start2[b];
    int cnt = g_start2[b + 1] - start;
    int cc = min(cnt, CAP);
    int size = (cc <= 256) ? 256 : CAP;
    float sc31 = sA[31], sh31 = sB[31];

    // ---- phase 1: compute keys (identical summation to old k_gkey) ----
    for (int rr = t; rr < size; rr += 256) {
        unsigned long long key = 0xFFFFFFFFFFFFFFFFull;
        if (rr < cc) {
            int n = start + rr;
            int beg = __ldg(&g_rowstart[n]);
            int end = __ldg(&g_rowstart[n + 1]);
            float acc = 0.f;
            int r = beg;
            while (r + 8 <= end) {
                int idx[8];
#pragma unroll
                for (int j = 0; j < 8; j++) idx[j] = __ldg(&g_csrsrc[r + j]);
                float hv[8];
#pragma unroll
                for (int j = 0; j < 8; j++) hv[j] = __ldg(&g_c31[idx[j]]);
                acc += (((hv[0] + hv[1]) + (hv[2] + hv[3])) +
                        ((hv[4] + hv[5]) + (hv[6] + hv[7])));
                r += 8;
            }
            if (r + 4 <= end) {
                int idx[4];
#pragma unroll
                for (int j = 0; j < 4; j++) idx[j] = __ldg(&g_csrsrc[r + j]);
                float hv[4];
#pragma unroll
                for (int j = 0; j < 4; j++) hv[j] = __ldg(&g_c31[idx[j]]);
                acc += ((hv[0] + hv[1]) + (hv[2] + hv[3]));
                r += 4;
            }
            for (; r < end; r++)
                acc += __ldg(&g_c31[__ldg(&g_csrsrc[r])]);
            acc += __ldg(&g_c31[n]);   // self last

            float v = fmaxf(fmaf(acc * g_dinv[n], sc31, sh31), 0.f);
            unsigned u = (v == 0.0f) ? 0u : __float_as_uint(v);
            key = ((unsigned long long)(~u) << 32) | (unsigned)rr;
        }
        keys[rr] = key;
    }
    __syncthreads();

    // ---- phase 2: bitonic sort ----
    if (size == 256) {
        for (int k = 2; k <= 256; k <<= 1) {
            for (int j = k >> 1; j > 0; j >>= 1) {
                int i = t;
                int ixj = i ^ j;
                if (ixj > i) {
                    unsigned long long a = keys[i], c = keys[ixj];
                    bool up = ((i & k) == 0);
                    bool sw = up ? (a > c) : (a < c);
                    if (sw) { keys[i] = c; keys[ixj] = a; }
                }
                __syncthreads();
            }
        }
    } else {
        for (int k = 2; k <= CAP; k <<= 1) {
            for (int j = k >> 1; j > 0; j >>= 1) {
                for (int base = 0; base < CAP; base += 256) {
                    int i = base + t;
                    int ixj = i ^ j;
                    if (ixj > i) {
                        unsigned long long a = keys[i], c = keys[ixj];
                        bool up = ((i & k) == 0);
                        bool sw = up ? (a > c) : (a < c);
                        if (sw) { keys[i] = c; keys[ixj] = a; }
                    }
                }
                __syncthreads();
            }
        }
    }

    int nval = min(cc, KK);
    if (t < KK)
        ssel[t] = (t < nval) ? start + (int)(unsigned)(keys[t] & 0xFFFFFFFFu) : -1;
    __syncthreads();

    // ---- phase 3: full gather for selected nodes (identical to k_gsel) ----
    if (t < KK * 8) {
        int slot = t >> 3;
        int p = t & 7;
        int n = ssel[slot];
        float4* outp = (float4*)(g_pooled + (size_t)(b * KK + slot) * HH) + p;
        if (n < 0) {
            *outp = make_float4(0.f, 0.f, 0.f, 0.f);
        } else {
            const float4* hp = (const float4*)g_ha;
            int beg = __ldg(&g_rowstart[n]);
            int end = __ldg(&g_rowstart[n + 1]);
            float4 acc = make_float4(0.f, 0.f, 0.f, 0.f);
            int r = beg;
            while (r + 8 <= end) {
                int idx[8];
#pragma unroll
                for (int j = 0; j < 8; j++) idx[j] = __ldg(&g_csrsrc[r + j]);
                float4 hv[8];
#pragma unroll
                for (int j = 0; j < 8; j++) hv[j] = __ldg(hp + (size_t)idx[j] * 8 + p);
                acc = add4(acc, add4(add4(add4(hv[0], hv[1]), add4(hv[2], hv[3])),
                                     add4(add4(hv[4], hv[5]), add4(hv[6], hv[7]))));
                r += 8;
            }
            if (r + 4 <= end) {
                int idx[4];
#pragma unroll
                for (int j = 0; j < 4; j++) idx[j] = __ldg(&g_csrsrc[r + j]);
                float4 hv[4];
#pragma unroll
                for (int j = 0; j < 4; j++) hv[j] = __ldg(hp + (size_t)idx[j] * 8 + p);
                acc = add4(acc, add4(add4(hv[0], hv[1]), add4(hv[2], hv[3])));
                r += 4;
            }
            for (; r < end; r++) {
                int s = __ldg(&g_csrsrc[r]);
                acc = add4(acc, __ldg(hp + (size_t)s * 8 + p));
            }
            acc = add4(acc, __ldg(hp + (size_t)n * 8 + p));   // self last

            float dn = g_dinv[n];
            float4 xv;
            xv.x = fmaxf(fmaf(acc.x * dn, sA[4 * p + 0], sB[4 * p + 0]), 0.f);
            xv.y = fmaxf(fmaf(acc.y * dn, sA[4 * p + 1], sB[4 * p + 1]), 0.f);
            xv.z = fmaxf(fmaf(acc.z * dn, sA[4 * p + 2], sB[4 * p + 2]), 0.f);
            xv.w = fmaxf(fmaf(acc.w * dn, sA[4 * p + 3], sB[4 * p + 3]), 0.f);
            *outp = xv;
        }
    }
}

// ---------------- MLP head: block-tiled, 32 graphs/block --------------------
__global__ void __launch_bounds__(256) k_mlp(
    const float* __restrict__ W1, const float* __restrict__ b1,
    const float* __restrict__ W2, const float* __restrict__ b2,
    const float* __restrict__ W3, const float* __restrict__ b3,
    float* __restrict__ out)
{
    __shared__ float  Xs[32][33];
    __shared__ float4 Wt[32][8];
    __shared__ float  H1[32][33];
    int t = threadIdx.x;
    int tg = t >> 3, tj = t & 7;
    int g0 = blockIdx.x * 32;

    float4 accf = __ldg((const float4*)b1 + tj);
    unsigned long long a0 = pk2(accf.x, accf.y);
    unsigned long long a1 = pk2(accf.z, accf.w);

    for (int c = 0; c < 30; c++) {
        int p0 = c * 32;
        __syncthreads();
        float4 xv = __ldg((const float4*)(g_pooled + (size_t)(g0 + tg) * (KK * HH)
                                          + p0 + 4 * tj));
        Xs[tg][4 * tj + 0] = xv.x; Xs[tg][4 * tj + 1] = xv.y;
        Xs[tg][4 * tj + 2] = xv.z; Xs[tg][4 * tj + 3] = xv.w;
        Wt[tg][tj] = __ldg((const float4*)(W1 + (size_t)(p0 + tg) * 32 + 4 * tj));
        __syncthreads();
#pragma unroll
        for (int kk = 0; kk < 32; kk++) {
            float xk = Xs[tg][kk];
            unsigned long long xkk = pk2(xk, xk);
            float4 w = Wt[kk][tj];
            fma2(a0, xkk, pk2(w.x, w.y));
            fma2(a1, xkk, pk2(w.z, w.w));
        }
    }
    float r0, r1, r2, r3;
    asm("mov.b64 {%0,%1}, %2;" : "=f"(r0), "=f"(r1) : "l"(a0));
    asm("mov.b64 {%0,%1}, %2;" : "=f"(r2), "=f"(r3) : "l"(a1));
    H1[tg][4 * tj + 0] = fmaxf(r0, 0.f);
    H1[tg][4 * tj + 1] = fmaxf(r1, 0.f);
    H1[tg][4 * tj + 2] = fmaxf(r2, 0.f);
    H1[tg][4 * tj + 3] = fmaxf(r3, 0.f);
    __syncthreads();

    if (t < 32) {
        int g = t;
        float h2a[16];
#pragma unroll
        for (int m = 0; m < 16; m++) h2a[m] = b2[m];
#pragma unroll
        for (int h = 0; h < 32; h++) {
            float x = H1[g][h];
#pragma unroll
            for (int m = 0; m < 16; m++) h2a[m] = fmaf(x, W2[h * 16 + m], h2a[m]);
        }
        float o = b3[0];
#pragma unroll
        for (int m = 0; m < 16; m++) o = fmaf(fmaxf(h2a[m], 0.f), W3[m], o);
        out[g0 + g] = o;
    }
}

// ---------------- launch -----------------------------------------------------
extern "C" void kernel_launch(void* const* d_in, const int* in_sizes, int n_in,
                              void* d_out, int out_size) {
    const int*   xz    = (const int*)d_in[0];
    const int*   ei    = (const int*)d_in[1];
    const int*   batch = (const int*)d_in[2];
    const float* emb   = (const float*)d_in[3];
    const float* Wc    = (const float*)d_in[4];
    const float* bc    = (const float*)d_in[5];
    const float* gamma = (const float*)d_in[6];
    const float* beta  = (const float*)d_in[7];
    const float* rmean = (const float*)d_in[8];
    const float* rvar  = (const float*)d_in[9];
    const float* W1    = (const float*)d_in[10];
    const float* b1    = (const float*)d_in[11];
    const float* W2    = (const float*)d_in[12];
    const float* b2    = (const float*)d_in[13];
    const float* W3    = (const float*)d_in[14];
    const float* b3    = (const float*)d_in[15];
    float* out = (float*)d_out;

    const int* src = ei;
    const int* dst = ei + EE;

    k_embw    <<<NBLK, 256>>>(emb, Wc);                                   // 1
    k_degb    <<<EE / 1024, 256>>>(dst);                                  // 2
    k_scanA   <<<NBLK, 256>>>(xz, batch);                                 // 3
    k_scanB   <<<NBLK, 256>>>();                                          // 4
    k_fill    <<<EE / 1024, 256>>>(src, dst);                             // 5
    k_sortval <<<NBLK, 256>>>();                                          // 6
    k_gbg0    <<<(NN * 8) / 256, 256>>>(Wc, bc, gamma, beta, rmean, rvar);// 7
    k_gbg     <<<(NN * 8) / 256, 256>>>(Wc, bc, gamma, beta, rmean, rvar);// 8
    k_sortpool<<<BB, 256>>>(bc, gamma, beta, rmean, rvar);                // 9
    k_mlp     <<<BB / 32, 256>>>(W1, b1, W2, b2, W3, b3, out);            // 10
}

// round 15
// speedup vs baseline: 1.0697x; 1.0037x over previous
#include <cuda_runtime.h>

#define NN 524288
#define EE 4194304
#define BB 4096
#define HH 32
#define KK 30
#define CAP 512
#define MAXZ1 1001
#define EPSF 1e-5f
#define NBLK 2048          // NN/256

// ---------------- scratch (device globals; no allocation allowed) ----------
__device__ int   g_deg[NN];
__device__ float g_dinv[NN];
__device__ int2  g_pack[NN];              // {xz, dinv bits}
__device__ float g_embw[MAXZ1 * HH];      // emb @ W0   (128KB)
__device__ float g_ha[(size_t)NN * HH];   // layer1 out
__device__ float g_hb[(size_t)NN * HH];   // layer0 out
__device__ float g_c31[NN];               // h' channel 31 sidecar (L2-resident)
__device__ int   g_rowstart[NN + 1];
__device__ int   g_cursor[NN];
__device__ int   g_csrsrc[EE];
__device__ int   g_bsum[NBLK];
__device__ int   g_start2[BB + 1];
__device__ float g_pooled[(size_t)BB * KK * HH];

__device__ __forceinline__ float4 add4(float4 a, float4 b) {
    return make_float4(a.x + b.x, a.y + b.y, a.z + b.z, a.w + b.w);
}
__device__ __forceinline__ float4 scale4(float4 a, float s) {
    return make_float4(a.x * s, a.y * s, a.z * s, a.w * s);
}
__device__ __forceinline__ unsigned long long pk2(float x, float y) {
    unsigned long long r;
    asm("mov.b64 %0, {%1,%2};" : "=l"(r) : "f"(x), "f"(y));
    return r;
}
__device__ __forceinline__ void fma2(unsigned long long& d, unsigned long long a,
                                     unsigned long long b) {
    asm("fma.rn.f32x2 %0, %1, %2, %0;" : "+l"(d) : "l"(a), "l"(b));
}
__device__ __forceinline__ unsigned long long mul2(unsigned long long a,
                                                   unsigned long long b) {
    unsigned long long r;
    asm("mul.rn.f32x2 %0, %1, %2;" : "=l"(r) : "l"(a), "l"(b));
    return r;
}

// ---------------- embW0 = emb @ Wc[0] (126 blocks only) ---------------------
__global__ void __launch_bounds__(256) k_embw(
    const float* __restrict__ emb, const float* __restrict__ Wc)
{
    __shared__ float Ws[HH * HH];
    int t = threadIdx.x;
    int b = blockIdx.x;
    for (int i = t; i < HH * HH; i += 256) Ws[i] = Wc[i];
    __syncthreads();
    int row = b * 8 + (t >> 5);
    int col = t & 31;
    if (row < MAXZ1) {
        const float* er = emb + (size_t)row * HH;
        float acc = 0.f;
#pragma unroll
        for (int k = 0; k < HH; k++) acc = fmaf(er[k], Ws[k * HH + col], acc);
        g_embw[row * HH + col] = acc;
    }
}

// in-degree histogram, 4 edges/thread
__global__ void k_degb(const int* __restrict__ dst) {
    int i = blockIdx.x * 256 + threadIdx.x;   // grid covers EE/4
    int4 d = ((const int4*)dst)[i];
    atomicAdd(&g_deg[d.x], 1);
    atomicAdd(&g_deg[d.y], 1);
    atomicAdd(&g_deg[d.z], 1);
    atomicAdd(&g_deg[d.w], 1);
}

// scanA: block sums of deg + dinv + pack{xz,dinv} + graph boundaries
__global__ void k_scanA(const int* __restrict__ xz, const int* __restrict__ batch) {
    __shared__ int s[256];
    int t = threadIdx.x;
    int i = blockIdx.x * 256 + t;
    int d = g_deg[i];
    float dn = rsqrtf((float)d + 1.0f);
    g_dinv[i] = dn;
    g_pack[i] = make_int2(xz[i], __float_as_int(dn));
    {
        int b1 = batch[i];
        int b0 = (i > 0) ? batch[i - 1] : -1;
        for (int b = b0 + 1; b <= b1; b++) g_start2[b] = i;
        if (i == NN - 1)
            for (int b = b1 + 1; b <= BB; b++) g_start2[b] = NN;
    }
    s[t] = d;
    __syncthreads();
    for (int off = 128; off; off >>= 1) {
        if (t < off) s[t] += s[t + off];
        __syncthreads();
    }
    if (t == 0) g_bsum[blockIdx.x] = s[0];
}

// scanB: each block sums its bsum prefix directly, then local scan
__global__ void __launch_bounds__(256) k_scanB() {
    __shared__ int red[256];
    __shared__ int s[256];
    int b = blockIdx.x, t = threadIdx.x;
    int part = 0;
    for (int j = t; j < b; j += 256) part += g_bsum[j];
    red[t] = part;
    __syncthreads();
    for (int off = 128; off; off >>= 1) {
        if (t < off) red[t] += red[t + off];
        __syncthreads();
    }
    int base = red[0];
    int i = b * 256 + t;
    int d = g_deg[i];
    s[t] = d;
    __syncthreads();
    for (int off = 1; off < 256; off <<= 1) {
        int v = (t >= off) ? s[t - off] : 0;
        __syncthreads();
        s[t] += v;
        __syncthreads();
    }
    int excl = base + s[t] - d;
    g_rowstart[i] = excl;
    g_cursor[i] = excl;
    if (i == NN - 1) g_rowstart[NN] = EE;
}

// ---------------- CSR fill: 4 edges/thread ----------------------------------
__global__ void k_fill(const int* __restrict__ src, const int* __restrict__ dst) {
    int i = blockIdx.x * 256 + threadIdx.x;   // grid covers EE/4
    int4 sv = ((const int4*)src)[i];
    int4 dv = ((const int4*)dst)[i];
    g_csrsrc[atomicAdd(&g_cursor[dv.x], 1)] = sv.x;
    g_csrsrc[atomicAdd(&g_cursor[dv.y], 1)] = sv.y;
    g_csrsrc[atomicAdd(&g_cursor[dv.z], 1)] = sv.z;
    g_csrsrc[atomicAdd(&g_cursor[dv.w], 1)] = sv.w;
}

// ---------------- canonicalize rows: sort src values ascending --------------
__global__ void __launch_bounds__(256) k_sortval() {
    int n = blockIdx.x * 256 + threadIdx.x;
    int beg = g_rowstart[n];
    int len = g_rowstart[n + 1] - beg;
    if (len <= 1) return;
    if (len <= 16) {
        int v[16];
#pragma unroll
        for (int i = 0; i < 16; i++)
            v[i] = (i < len) ? g_csrsrc[beg + i] : 0x7FFFFFFF;
#pragma unroll
        for (int k = 2; k <= 16; k <<= 1) {
#pragma unroll
            for (int j = k >> 1; j > 0; j >>= 1) {
#pragma unroll
                for (int i = 0; i < 16; i++) {
                    int ix = i ^ j;
                    if (ix > i) {
                        bool up = ((i & k) == 0);
                        int a = v[i], c = v[ix];
                        bool sw = up ? (a > c) : (a < c);
                        if (sw) { v[i] = c; v[ix] = a; }
                    }
                }
            }
        }
        for (int i = 0; i < len; i++) g_csrsrc[beg + i] = v[i];
    } else {
        int end = beg + len;
        for (int i = beg + 1; i < end; i++) {
            int key = g_csrsrc[i];
            int j = i - 1;
            while (j >= beg && g_csrsrc[j] > key) {
                g_csrsrc[j + 1] = g_csrsrc[j];
                j--;
            }
            g_csrsrc[j + 1] = key;
        }
    }
}

// ---------------- layer 0 fused: table-gather + BN0 + ReLU + GEMM1 ----------
__global__ void __launch_bounds__(256) k_gbg0(
    const float* __restrict__ Wc, const float* __restrict__ bcp,
    const float* __restrict__ gamma, const float* __restrict__ beta,
    const float* __restrict__ rmean, const float* __restrict__ rvar)
{
    __shared__ ulonglong2 Ws2[HH * 8];
    __shared__ float sA[HH], sB[HH];
    __shared__ float xs[32 * 40];
    int t = threadIdx.x;
    if (t < HH * 8) Ws2[t] = ((const ulonglong2*)(Wc + 1 * HH * HH))[t];
    if (t < HH) {
        float sc = gamma[t] * rsqrtf(rvar[t] + EPSF);
        float sh = beta[t] - rmean[t] * sc;
        sA[t] = sc;
        sB[t] = fmaf(bcp[t], sc, sh);
    }
    __syncthreads();

    int tid = blockIdx.x * 256 + t;   // grid covers NN*8
    int n = tid >> 3;
    int p = tid & 7;
    int nl = t >> 3;
    const float4* ew = (const float4*)g_embw;

    int beg = __ldg(&g_rowstart[n]);
    int end = __ldg(&g_rowstart[n + 1]);

    float4 acc = make_float4(0.f, 0.f, 0.f, 0.f);
    int r = beg;
    while (r + 8 <= end) {
        int idx[8];
#pragma unroll
        for (int j = 0; j < 8; j++) idx[j] = __ldg(&g_csrsrc[r + j]);
        int2 pk[8];
#pragma unroll
        for (int j = 0; j < 8; j++) pk[j] = __ldg(&g_pack[idx[j]]);
        float4 hv[8];
#pragma unroll
        for (int j = 0; j < 8; j++)
            hv[j] = scale4(__ldg(ew + (size_t)pk[j].x * 8 + p),
                           __int_as_float(pk[j].y));
        acc = add4(acc, add4(add4(add4(hv[0], hv[1]), add4(hv[2], hv[3])),
                             add4(add4(hv[4], hv[5]), add4(hv[6], hv[7]))));
        r += 8;
    }
    if (r + 4 <= end) {
        int idx[4];
#pragma unroll
        for (int j = 0; j < 4; j++) idx[j] = __ldg(&g_csrsrc[r + j]);
        int2 pk[4];
#pragma unroll
        for (int j = 0; j < 4; j++) pk[j] = __ldg(&g_pack[idx[j]]);
        float4 hv[4];
#pragma unroll
        for (int j = 0; j < 4; j++)
            hv[j] = scale4(__ldg(ew + (size_t)pk[j].x * 8 + p),
                           __int_as_float(pk[j].y));
        acc = add4(acc, add4(add4(hv[0], hv[1]), add4(hv[2], hv[3])));
        r += 4;
    }
    for (; r < end; r++) {
        int s = __ldg(&g_csrsrc[r]);
        int2 pk = __ldg(&g_pack[s]);
        acc = add4(acc, scale4(__ldg(ew + (size_t)pk.x * 8 + p),
                               __int_as_float(pk.y)));
    }
    // self term last (matches reference order)
    int2 pks = __ldg(&g_pack[n]);
    float dn = __int_as_float(pks.y);
    acc = add4(acc, scale4(__ldg(ew + (size_t)pks.x * 8 + p), dn));

    float4 xv;
    xv.x = fmaxf(fmaf(acc.x * dn, sA[4 * p + 0], sB[4 * p + 0]), 0.f);
    xv.y = fmaxf(fmaf(acc.y * dn, sA[4 * p + 1], sB[4 * p + 1]), 0.f);
    xv.z = fmaxf(fmaf(acc.z * dn, sA[4 * p + 2], sB[4 * p + 2]), 0.f);
    xv.w = fmaxf(fmaf(acc.w * dn, sA[4 * p + 3], sB[4 * p + 3]), 0.f);
    *(float4*)(xs + nl * 40 + 4 * p) = xv;
    __syncwarp();   // exchange partners are within this warp only

    const float* xrow = xs + nl * 40;
    unsigned long long a0 = 0ULL, a1 = 0ULL;
#pragma unroll
    for (int k = 0; k < HH; k++) {
        float xk = xrow[k];                  // scalar LDS, conflict-free
        unsigned long long xkk = pk2(xk, xk);
        ulonglong2 w = Ws2[k * 8 + p];
        fma2(a0, xkk, w.x);
        fma2(a1, xkk, w.y);
    }
    unsigned long long dn2 = pk2(dn, dn);
    ((ulonglong2*)(g_hb + (size_t)n * HH))[p] =
        make_ulonglong2(mul2(a0, dn2), mul2(a1, dn2));
}

// ---------------- layer 1 fused: gather(hb) + BN1 + ReLU + GEMM2 -> ha ------
// Also writes channel-31 sidecar g_c31 (bit-identical value).
__global__ void __launch_bounds__(256) k_gbg(
    const float* __restrict__ Wc, const float* __restrict__ bcp,
    const float* __restrict__ gamma, const float* __restrict__ beta,
    const float* __restrict__ rmean, const float* __restrict__ rvar)
{
    __shared__ ulonglong2 Ws2[HH * 8];
    __shared__ float sA[HH], sB[HH];
    __shared__ float xs[32 * 40];
    int t = threadIdx.x;
    if (t < HH * 8) Ws2[t] = ((const ulonglong2*)(Wc + 2 * HH * HH))[t];
    if (t < HH) {
        float sc = gamma[HH + t] * rsqrtf(rvar[HH + t] + EPSF);
        float sh = beta[HH + t] - rmean[HH + t] * sc;
        sA[t] = sc;
        sB[t] = fmaf(bcp[HH + t], sc, sh);
    }
    __syncthreads();

    int tid = blockIdx.x * 256 + t;   // grid covers NN*8
    int n = tid >> 3;
    int p = tid & 7;
    int nl = t >> 3;
    const float4* hp = (const float4*)g_hb;

    int beg = __ldg(&g_rowstart[n]);
    int end = __ldg(&g_rowstart[n + 1]);

    float4 acc = make_float4(0.f, 0.f, 0.f, 0.f);
    int r = beg;
    while (r + 8 <= end) {
        int idx[8];
#pragma unroll
        for (int j = 0; j < 8; j++) idx[j] = __ldg(&g_csrsrc[r + j]);
        float4 hv[8];
#pragma unroll
        for (int j = 0; j < 8; j++) hv[j] = __ldg(hp + (size_t)idx[j] * 8 + p);
        acc = add4(acc, add4(add4(add4(hv[0], hv[1]), add4(hv[2], hv[3])),
                             add4(add4(hv[4], hv[5]), add4(hv[6], hv[7]))));
        r += 8;
    }
    if (r + 4 <= end) {
        int idx[4];
#pragma unroll
        for (int j = 0; j < 4; j++) idx[j] = __ldg(&g_csrsrc[r + j]);
        float4 hv[4];
#pragma unroll
        for (int j = 0; j < 4; j++) hv[j] = __ldg(hp + (size_t)idx[j] * 8 + p);
        acc = add4(acc, add4(add4(hv[0], hv[1]), add4(hv[2], hv[3])));
        r += 4;
    }
    for (; r < end; r++) {
        int s = __ldg(&g_csrsrc[r]);
        acc = add4(acc, __ldg(hp + (size_t)s * 8 + p));
    }
    acc = add4(acc, __ldg(hp + (size_t)n * 8 + p));   // self last

    float dn = g_dinv[n];
    float4 xv;
    xv.x = fmaxf(fmaf(acc.x * dn, sA[4 * p + 0], sB[4 * p + 0]), 0.f);
    xv.y = fmaxf(fmaf(acc.y * dn, sA[4 * p + 1], sB[4 * p + 1]), 0.f);
    xv.z = fmaxf(fmaf(acc.z * dn, sA[4 * p + 2], sB[4 * p + 2]), 0.f);
    xv.w = fmaxf(fmaf(acc.w * dn, sA[4 * p + 3], sB[4 * p + 3]), 0.f);
    *(float4*)(xs + nl * 40 + 4 * p) = xv;
    __syncwarp();   // exchange partners are within this warp only

    const float* xrow = xs + nl * 40;
    unsigned long long a0 = 0ULL, a1 = 0ULL;
#pragma unroll
    for (int k = 0; k < HH; k++) {
        float xk = xrow[k];                  // scalar LDS, conflict-free
        unsigned long long xkk = pk2(xk, xk);
        ulonglong2 w = Ws2[k * 8 + p];
        fma2(a0, xkk, w.x);
        fma2(a1, xkk, w.y);
    }
    unsigned long long dn2 = pk2(dn, dn);
    unsigned long long o0 = mul2(a0, dn2);
    unsigned long long o1 = mul2(a1, dn2);
    ((ulonglong2*)(g_ha + (size_t)n * HH))[p] = make_ulonglong2(o0, o1);
    if (p == 7) {
        float lo, hi;
        asm("mov.b64 {%0,%1}, %2;" : "=f"(lo), "=f"(hi) : "l"(o1));
        g_c31[n] = hi;   // channel 31, bit-identical to g_ha[n*32+31]
    }
}

// ---------------- FUSED SortPool: key gather + sort + top-K full gather -----
__global__ void __launch_bounds__(256) k_sortpool(
    const float* __restrict__ bcp,
    const float* __restrict__ gamma, const float* __restrict__ beta,
    const float* __restrict__ rmean, const float* __restrict__ rvar)
{
    __shared__ unsigned long long keys[CAP];
    __shared__ int ssel[KK];
    __shared__ float sA[HH], sB[HH];
    int b = blockIdx.x, t = threadIdx.x;
    if (t < HH) {
        float sc = gamma[2 * HH + t] * rsqrtf(rvar[2 * HH + t] + EPSF);
        float sh = beta[2 * HH + t] - rmean[2 * HH + t] * sc;
        sA[t] = sc;
        sB[t] = fmaf(bcp[2 * HH + t], sc, sh);
    }
    __syncthreads();

    int start = g_start2[b];
    int cnt = g_start2[b + 1] - start;
    int cc = min(cnt, CAP);
    int size = (cc <= 256) ? 256 : CAP;
    float sc31 = sA[31], sh31 = sB[31];

    // ---- phase 1: compute keys (identical summation to old k_gkey) ----
    for (int rr = t; rr < size; rr += 256) {
        unsigned long long key = 0xFFFFFFFFFFFFFFFFull;
        if (rr < cc) {
            int n = start + rr;
            int beg = __ldg(&g_rowstart[n]);
            int end = __ldg(&g_rowstart[n + 1]);
            float acc = 0.f;
            int r = beg;
            while (r + 8 <= end) {
                int idx[8];
#pragma unroll
                for (int j = 0; j < 8; j++) idx[j] = __ldg(&g_csrsrc[r + j]);
                float hv[8];
#pragma unroll
                for (int j = 0; j < 8; j++) hv[j] = __ldg(&g_c31[idx[j]]);
                acc += (((hv[0] + hv[1]) + (hv[2] + hv[3])) +
                        ((hv[4] + hv[5]) + (hv[6] + hv[7])));
                r += 8;
            }
            if (r + 4 <= end) {
                int idx[4];
#pragma unroll
                for (int j = 0; j < 4; j++) idx[j] = __ldg(&g_csrsrc[r + j]);
                float hv[4];
#pragma unroll
                for (int j = 0; j < 4; j++) hv[j] = __ldg(&g_c31[idx[j]]);
                acc += ((hv[0] + hv[1]) + (hv[2] + hv[3]));
                r += 4;
            }
            for (; r < end; r++)
                acc += __ldg(&g_c31[__ldg(&g_csrsrc[r])]);
            acc += __ldg(&g_c31[n]);   // self last

            float v = fmaxf(fmaf(acc * g_dinv[n], sc31, sh31), 0.f);
            unsigned u = (v == 0.0f) ? 0u : __float_as_uint(v);
            key = ((unsigned long long)(~u) << 32) | (unsigned)rr;
        }
        keys[rr] = key;
    }
    __syncthreads();

    // ---- phase 2: bitonic sort ----
    if (size == 256) {
        for (int k = 2; k <= 256; k <<= 1) {
            for (int j = k >> 1; j > 0; j >>= 1) {
                int i = t;
                int ixj = i ^ j;
                if (ixj > i) {
                    unsigned long long a = keys[i], c = keys[ixj];
                    bool up = ((i & k) == 0);
                    bool sw = up ? (a > c) : (a < c);
                    if (sw) { keys[i] = c; keys[ixj] = a; }
                }
                __syncthreads();
            }
        }
    } else {
        for (int k = 2; k <= CAP; k <<= 1) {
            for (int j = k >> 1; j > 0; j >>= 1) {
                for (int base = 0; base < CAP; base += 256) {
                    int i = base + t;
                    int ixj = i ^ j;
                    if (ixj > i) {
                        unsigned long long a = keys[i], c = keys[ixj];
                        bool up = ((i & k) == 0);
                        bool sw = up ? (a > c) : (a < c);
                        if (sw) { keys[i] = c; keys[ixj] = a; }
                    }
                }
                __syncthreads();
            }
        }
    }

    int nval = min(cc, KK);
    if (t < KK)
        ssel[t] = (t < nval) ? start + (int)(unsigned)(keys[t] & 0xFFFFFFFFu) : -1;
    __syncthreads();

    // ---- phase 3: full gather for selected nodes (identical to k_gsel) ----
    if (t < KK * 8) {
        int slot = t >> 3;
        int p = t & 7;
        int n = ssel[slot];
        float4* outp = (float4*)(g_pooled + (size_t)(b * KK + slot) * HH) + p;
        if (n < 0) {
            *outp = make_float4(0.f, 0.f, 0.f, 0.f);
        } else {
            const float4* hp = (const float4*)g_ha;
            int beg = __ldg(&g_rowstart[n]);
            int end = __ldg(&g_rowstart[n + 1]);
            float4 acc = make_float4(0.f, 0.f, 0.f, 0.f);
            int r = beg;
            while (r + 8 <= end) {
                int idx[8];
#pragma unroll
                for (int j = 0; j < 8; j++) idx[j] = __ldg(&g_csrsrc[r + j]);
                float4 hv[8];
#pragma unroll
                for (int j = 0; j < 8; j++) hv[j] = __ldg(hp + (size_t)idx[j] * 8 + p);
                acc = add4(acc, add4(add4(add4(hv[0], hv[1]), add4(hv[2], hv[3])),
                                     add4(add4(hv[4], hv[5]), add4(hv[6], hv[7]))));
                r += 8;
            }
            if (r + 4 <= end) {
                int idx[4];
#pragma unroll
                for (int j = 0; j < 4; j++) idx[j] = __ldg(&g_csrsrc[r + j]);
                float4 hv[4];
#pragma unroll
                for (int j = 0; j < 4; j++) hv[j] = __ldg(hp + (size_t)idx[j] * 8 + p);
                acc = add4(acc, add4(add4(hv[0], hv[1]), add4(hv[2], hv[3])));
                r += 4;
            }
            for (; r < end; r++) {
                int s = __ldg(&g_csrsrc[r]);
                acc = add4(acc, __ldg(hp + (size_t)s * 8 + p));
            }
            acc = add4(acc, __ldg(hp + (size_t)n * 8 + p));   // self last

            float dn = g_dinv[n];
            float4 xv;
            xv.x = fmaxf(fmaf(acc.x * dn, sA[4 * p + 0], sB[4 * p + 0]), 0.f);
            xv.y = fmaxf(fmaf(acc.y * dn, sA[4 * p + 1], sB[4 * p + 1]), 0.f);
            xv.z = fmaxf(fmaf(acc.z * dn, sA[4 * p + 2], sB[4 * p + 2]), 0.f);
            xv.w = fmaxf(fmaf(acc.w * dn, sA[4 * p + 3], sB[4 * p + 3]), 0.f);
            *outp = xv;
        }
    }
}

// ---------------- MLP head: block-tiled, 32 graphs/block --------------------
__global__ void __launch_bounds__(256) k_mlp(
    const float* __restrict__ W1, const float* __restrict__ b1,
    const float* __restrict__ W2, const float* __restrict__ b2,
    const float* __restrict__ W3, const float* __restrict__ b3,
    float* __restrict__ out)
{
    __shared__ float  Xs[32][33];
    __shared__ float4 Wt[32][8];
    __shared__ float  H1[32][33];
    int t = threadIdx.x;
    int tg = t >> 3, tj = t & 7;
    int g0 = blockIdx.x * 32;

    float4 accf = __ldg((const float4*)b1 + tj);
    unsigned long long a0 = pk2(accf.x, accf.y);
    unsigned long long a1 = pk2(accf.z, accf.w);

    for (int c = 0; c < 30; c++) {
        int p0 = c * 32;
        __syncthreads();
        float4 xv = __ldg((const float4*)(g_pooled + (size_t)(g0 + tg) * (KK * HH)
                                          + p0 + 4 * tj));
        Xs[tg][4 * tj + 0] = xv.x; Xs[tg][4 * tj + 1] = xv.y;
        Xs[tg][4 * tj + 2] = xv.z; Xs[tg][4 * tj + 3] = xv.w;
        Wt[tg][tj] = __ldg((const float4*)(W1 + (size_t)(p0 + tg) * 32 + 4 * tj));
        __syncthreads();
#pragma unroll
        for (int kk = 0; kk < 32; kk++) {
            float xk = Xs[tg][kk];
            unsigned long long xkk = pk2(xk, xk);
            float4 w = Wt[kk][tj];
            fma2(a0, xkk, pk2(w.x, w.y));
            fma2(a1, xkk, pk2(w.z, w.w));
        }
    }
    float r0, r1, r2, r3;
    asm("mov.b64 {%0,%1}, %2;" : "=f"(r0), "=f"(r1) : "l"(a0));
    asm("mov.b64 {%0,%1}, %2;" : "=f"(r2), "=f"(r3) : "l"(a1));
    H1[tg][4 * tj + 0] = fmaxf(r0, 0.f);
    H1[tg][4 * tj + 1] = fmaxf(r1, 0.f);
    H1[tg][4 * tj + 2] = fmaxf(r2, 0.f);
    H1[tg][4 * tj + 3] = fmaxf(r3, 0.f);
    __syncthreads();

    if (t < 32) {
        int g = t;
        float h2a[16];
#pragma unroll
        for (int m = 0; m < 16; m++) h2a[m] = b2[m];
#pragma unroll
        for (int h = 0; h < 32; h++) {
            float x = H1[g][h];
#pragma unroll
            for (int m = 0; m < 16; m++) h2a[m] = fmaf(x, W2[h * 16 + m], h2a[m]);
        }
        float o = b3[0];
#pragma unroll
        for (int m = 0; m < 16; m++) o = fmaf(fmaxf(h2a[m], 0.f), W3[m], o);
        out[g0 + g] = o;
    }
}

// ---------------- launch -----------------------------------------------------
extern "C" void kernel_launch(void* const* d_in, const int* in_sizes, int n_in,
                              void* d_out, int out_size) {
    const int*   xz    = (const int*)d_in[0];
    const int*   ei    = (const int*)d_in[1];
    const int*   batch = (const int*)d_in[2];
    const float* emb   = (const float*)d_in[3];
    const float* Wc    = (const float*)d_in[4];
    const float* bc    = (const float*)d_in[5];
    const float* gamma = (const float*)d_in[6];
    const float* beta  = (const float*)d_in[7];
    const float* rmean = (const float*)d_in[8];
    const float* rvar  = (const float*)d_in[9];
    const float* W1    = (const float*)d_in[10];
    const float* b1    = (const float*)d_in[11];
    const float* W2    = (const float*)d_in[12];
    const float* b2    = (const float*)d_in[13];
    const float* W3    = (const float*)d_in[14];
    const float* b3    = (const float*)d_in[15];
    float* out = (float*)d_out;

    const int* src = ei;
    const int* dst = ei + EE;

    void* degptr = nullptr;
    cudaGetSymbolAddress(&degptr, g_deg);
    cudaMemsetAsync(degptr, 0, NN * sizeof(int));                         // 1

    k_degb    <<<EE / 1024, 256>>>(dst);                                  // 2
    k_scanA   <<<NBLK, 256>>>(xz, batch);                                 // 3
    k_scanB   <<<NBLK, 256>>>();                                          // 4
    k_fill    <<<EE / 1024, 256>>>(src, dst);                             // 5
    k_sortval <<<NBLK, 256>>>();                                          // 6
    k_embw    <<<(MAXZ1 + 7) / 8, 256>>>(emb, Wc);                        // 7
    k_gbg0    <<<(NN * 8) / 256, 256>>>(Wc, bc, gamma, beta, rmean, rvar);// 8
    k_gbg     <<<(NN * 8) / 256, 256>>>(Wc, bc, gamma, beta, rmean, rvar);// 9
    k_sortpool<<<BB, 256>>>(bc, gamma, beta, rmean, rvar);                // 10
    k_mlp     <<<BB / 32, 256>>>(W1, b1, W2, b2, W3, b3, out);            // 11
}

// round 16
// speedup vs baseline: 1.0711x; 1.0013x over previous
#include <cuda_runtime.h>

#define NN 524288
#define EE 4194304
#define BB 4096
#define HH 32
#define KK 30
#define CAP 512
#define MAXZ1 1001
#define EPSF 1e-5f
#define NBLK 2048          // NN/256

// ---------------- scratch (device globals; no allocation allowed) ----------
__device__ int   g_deg[NN];
__device__ float g_dinv[NN];
__device__ int2  g_pack[NN];              // {xz, dinv bits}
__device__ float g_embw[MAXZ1 * HH];      // emb @ W0   (128KB)
__device__ float g_ha[(size_t)NN * HH];   // layer1 out
__device__ float g_hb[(size_t)NN * HH];   // layer0 out
__device__ float g_c31[NN];               // h' channel 31 sidecar (L2-resident)
__device__ int   g_rowstart[NN + 1];
__device__ int   g_rank[EE];              // per-edge slot rank within its dst row
__device__ int   g_csrsrc[EE];
__device__ int   g_bsum[NBLK];
__device__ int   g_start2[BB + 1];
__device__ float g_pooled[(size_t)BB * KK * HH];

__device__ __forceinline__ float4 add4(float4 a, float4 b) {
    return make_float4(a.x + b.x, a.y + b.y, a.z + b.z, a.w + b.w);
}
__device__ __forceinline__ float4 scale4(float4 a, float s) {
    return make_float4(a.x * s, a.y * s, a.z * s, a.w * s);
}
__device__ __forceinline__ unsigned long long pk2(float x, float y) {
    unsigned long long r;
    asm("mov.b64 %0, {%1,%2};" : "=l"(r) : "f"(x), "f"(y));
    return r;
}
__device__ __forceinline__ void fma2(unsigned long long& d, unsigned long long a,
                                     unsigned long long b) {
    asm("fma.rn.f32x2 %0, %1, %2, %0;" : "+l"(d) : "l"(a), "l"(b));
}
__device__ __forceinline__ unsigned long long mul2(unsigned long long a,
                                                   unsigned long long b) {
    unsigned long long r;
    asm("mul.rn.f32x2 %0, %1, %2;" : "=l"(r) : "l"(a), "l"(b));
    return r;
}

// ---------------- embW0 = emb @ Wc[0] (126 blocks only) ---------------------
__global__ void __launch_bounds__(256) k_embw(
    const float* __restrict__ emb, const float* __restrict__ Wc)
{
    __shared__ float Ws[HH * HH];
    int t = threadIdx.x;
    int b = blockIdx.x;
    for (int i = t; i < HH * HH; i += 256) Ws[i] = Wc[i];
    __syncthreads();
    int row = b * 8 + (t >> 5);
    int col = t & 31;
    if (row < MAXZ1) {
        const float* er = emb + (size_t)row * HH;
        float acc = 0.f;
#pragma unroll
        for (int k = 0; k < HH; k++) acc = fmaf(er[k], Ws[k * HH + col], acc);
        g_embw[row * HH + col] = acc;
    }
}

// in-degree histogram + per-edge rank, 4 edges/thread
__global__ void k_degb(const int* __restrict__ dst) {
    int i = blockIdx.x * 256 + threadIdx.x;   // grid covers EE/4
    int4 d = ((const int4*)dst)[i];
    int4 rk;
    rk.x = atomicAdd(&g_deg[d.x], 1);
    rk.y = atomicAdd(&g_deg[d.y], 1);
    rk.z = atomicAdd(&g_deg[d.z], 1);
    rk.w = atomicAdd(&g_deg[d.w], 1);
    ((int4*)g_rank)[i] = rk;
}

// scanA: block sums of deg + dinv + pack{xz,dinv} + graph boundaries
__global__ void k_scanA(const int* __restrict__ xz, const int* __restrict__ batch) {
    __shared__ int s[256];
    int t = threadIdx.x;
    int i = blockIdx.x * 256 + t;
    int d = g_deg[i];
    float dn = rsqrtf((float)d + 1.0f);
    g_dinv[i] = dn;
    g_pack[i] = make_int2(xz[i], __float_as_int(dn));
    {
        int b1 = batch[i];
        int b0 = (i > 0) ? batch[i - 1] : -1;
        for (int b = b0 + 1; b <= b1; b++) g_start2[b] = i;
        if (i == NN - 1)
            for (int b = b1 + 1; b <= BB; b++) g_start2[b] = NN;
    }
    s[t] = d;
    __syncthreads();
    for (int off = 128; off; off >>= 1) {
        if (t < off) s[t] += s[t + off];
        __syncthreads();
    }
    if (t == 0) g_bsum[blockIdx.x] = s[0];
}

// scanB: each block sums its bsum prefix directly, then local scan
__global__ void __launch_bounds__(256) k_scanB() {
    __shared__ int red[256];
    __shared__ int s[256];
    int b = blockIdx.x, t = threadIdx.x;
    int part = 0;
    for (int j = t; j < b; j += 256) part += g_bsum[j];
    red[t] = part;
    __syncthreads();
    for (int off = 128; off; off >>= 1) {
        if (t < off) red[t] += red[t + off];
        __syncthreads();
    }
    int base = red[0];
    int i = b * 256 + t;
    int d = g_deg[i];
    s[t] = d;
    __syncthreads();
    for (int off = 1; off < 256; off <<= 1) {
        int v = (t >= off) ? s[t - off] : 0;
        __syncthreads();
        s[t] += v;
        __syncthreads();
    }
    int excl = base + s[t] - d;
    g_rowstart[i] = excl;
    if (i == NN - 1) g_rowstart[NN] = EE;
}

// ---------------- CSR fill: NO atomics (pos = rowstart[dst] + rank[e]) ------
__global__ void k_fill(const int* __restrict__ src, const int* __restrict__ dst) {
    int i = blockIdx.x * 256 + threadIdx.x;   // grid covers EE/4
    int4 sv = ((const int4*)src)[i];
    int4 dv = ((const int4*)dst)[i];
    int4 rk = ((const int4*)g_rank)[i];
    g_csrsrc[__ldg(&g_rowstart[dv.x]) + rk.x] = sv.x;
    g_csrsrc[__ldg(&g_rowstart[dv.y]) + rk.y] = sv.y;
    g_csrsrc[__ldg(&g_rowstart[dv.z]) + rk.z] = sv.z;
    g_csrsrc[__ldg(&g_rowstart[dv.w]) + rk.w] = sv.w;
}

// ---------------- canonicalize rows: sort src values ascending --------------
__global__ void __launch_bounds__(256) k_sortval() {
    int n = blockIdx.x * 256 + threadIdx.x;
    int beg = g_rowstart[n];
    int len = g_rowstart[n + 1] - beg;
    if (len <= 1) return;
    if (len <= 16) {
        int v[16];
#pragma unroll
        for (int i = 0; i < 16; i++)
            v[i] = (i < len) ? g_csrsrc[beg + i] : 0x7FFFFFFF;
#pragma unroll
        for (int k = 2; k <= 16; k <<= 1) {
#pragma unroll
            for (int j = k >> 1; j > 0; j >>= 1) {
#pragma unroll
                for (int i = 0; i < 16; i++) {
                    int ix = i ^ j;
                    if (ix > i) {
                        bool up = ((i & k) == 0);
                        int a = v[i], c = v[ix];
                        bool sw = up ? (a > c) : (a < c);
                        if (sw) { v[i] = c; v[ix] = a; }
                    }
                }
            }
        }
        for (int i = 0; i < len; i++) g_csrsrc[beg + i] = v[i];
    } else {
        int end = beg + len;
        for (int i = beg + 1; i < end; i++) {
            int key = g_csrsrc[i];
            int j = i - 1;
            while (j >= beg && g_csrsrc[j] > key) {
                g_csrsrc[j + 1] = g_csrsrc[j];
                j--;
            }
            g_csrsrc[j + 1] = key;
        }
    }
}

// ---------------- layer 0 fused: table-gather + BN0 + ReLU + GEMM1 ----------
__global__ void __launch_bounds__(256) k_gbg0(
    const float* __restrict__ Wc, const float* __restrict__ bcp,
    const float* __restrict__ gamma, const float* __restrict__ beta,
    const float* __restrict__ rmean, const float* __restrict__ rvar)
{
    __shared__ ulonglong2 Ws2[HH * 8];
    __shared__ float sA[HH], sB[HH];
    __shared__ float xs[32 * 40];
    int t = threadIdx.x;
    if (t < HH * 8) Ws2[t] = ((const ulonglong2*)(Wc + 1 * HH * HH))[t];
    if (t < HH) {
        float sc = gamma[t] * rsqrtf(rvar[t] + EPSF);
        float sh = beta[t] - rmean[t] * sc;
        sA[t] = sc;
        sB[t] = fmaf(bcp[t], sc, sh);
    }
    __syncthreads();

    int tid = blockIdx.x * 256 + t;   // grid covers NN*8
    int n = tid >> 3;
    int p = tid & 7;
    int nl = t >> 3;
    const float4* ew = (const float4*)g_embw;

    int beg = __ldg(&g_rowstart[n]);
    int end = __ldg(&g_rowstart[n + 1]);

    float4 acc = make_float4(0.f, 0.f, 0.f, 0.f);
    int r = beg;
    while (r + 8 <= end) {
        int idx[8];
#pragma unroll
        for (int j = 0; j < 8; j++) idx[j] = __ldg(&g_csrsrc[r + j]);
        int2 pk[8];
#pragma unroll
        for (int j = 0; j < 8; j++) pk[j] = __ldg(&g_pack[idx[j]]);
        float4 hv[8];
#pragma unroll
        for (int j = 0; j < 8; j++)
            hv[j] = scale4(__ldg(ew + (size_t)pk[j].x * 8 + p),
                           __int_as_float(pk[j].y));
        acc = add4(acc, add4(add4(add4(hv[0], hv[1]), add4(hv[2], hv[3])),
                             add4(add4(hv[4], hv[5]), add4(hv[6], hv[7]))));
        r += 8;
    }
    if (r + 4 <= end) {
        int idx[4];
#pragma unroll
        for (int j = 0; j < 4; j++) idx[j] = __ldg(&g_csrsrc[r + j]);
        int2 pk[4];
#pragma unroll
        for (int j = 0; j < 4; j++) pk[j] = __ldg(&g_pack[idx[j]]);
        float4 hv[4];
#pragma unroll
        for (int j = 0; j < 4; j++)
            hv[j] = scale4(__ldg(ew + (size_t)pk[j].x * 8 + p),
                           __int_as_float(pk[j].y));
        acc = add4(acc, add4(add4(hv[0], hv[1]), add4(hv[2], hv[3])));
        r += 4;
    }
    for (; r < end; r++) {
        int s = __ldg(&g_csrsrc[r]);
        int2 pk = __ldg(&g_pack[s]);
        acc = add4(acc, scale4(__ldg(ew + (size_t)pk.x * 8 + p),
                               __int_as_float(pk.y)));
    }
    // self term last (matches reference order)
    int2 pks = __ldg(&g_pack[n]);
    float dn = __int_as_float(pks.y);
    acc = add4(acc, scale4(__ldg(ew + (size_t)pks.x * 8 + p), dn));

    float4 xv;
    xv.x = fmaxf(fmaf(acc.x * dn, sA[4 * p + 0], sB[4 * p + 0]), 0.f);
    xv.y = fmaxf(fmaf(acc.y * dn, sA[4 * p + 1], sB[4 * p + 1]), 0.f);
    xv.z = fmaxf(fmaf(acc.z * dn, sA[4 * p + 2], sB[4 * p + 2]), 0.f);
    xv.w = fmaxf(fmaf(acc.w * dn, sA[4 * p + 3], sB[4 * p + 3]), 0.f);
    *(float4*)(xs + nl * 40 + 4 * p) = xv;
    __syncwarp();   // exchange partners are within this warp only

    const float* xrow = xs + nl * 40;
    unsigned long long a0 = 0ULL, a1 = 0ULL;
#pragma unroll
    for (int k = 0; k < HH; k++) {
        float xk = xrow[k];                  // scalar LDS, conflict-free
        unsigned long long xkk = pk2(xk, xk);
        ulonglong2 w = Ws2[k * 8 + p];
        fma2(a0, xkk, w.x);
        fma2(a1, xkk, w.y);
    }
    unsigned long long dn2 = pk2(dn, dn);
    ((ulonglong2*)(g_hb + (size_t)n * HH))[p] =
        make_ulonglong2(mul2(a0, dn2), mul2(a1, dn2));
}

// ---------------- layer 1 fused: gather(hb) + BN1 + ReLU + GEMM2 -> ha ------
// Also writes channel-31 sidecar g_c31 (bit-identical value).
__global__ void __launch_bounds__(256) k_gbg(
    const float* __restrict__ Wc, const float* __restrict__ bcp,
    const float* __restrict__ gamma, const float* __restrict__ beta,
    const float* __restrict__ rmean, const float* __restrict__ rvar)
{
    __shared__ ulonglong2 Ws2[HH * 8];
    __shared__ float sA[HH], sB[HH];
    __shared__ float xs[32 * 40];
    int t = threadIdx.x;
    if (t < HH * 8) Ws2[t] = ((const ulonglong2*)(Wc + 2 * HH * HH))[t];
    if (t < HH) {
        float sc = gamma[HH + t] * rsqrtf(rvar[HH + t] + EPSF);
        float sh = beta[HH + t] - rmean[HH + t] * sc;
        sA[t] = sc;
        sB[t] = fmaf(bcp[HH + t], sc, sh);
    }
    __syncthreads();

    int tid = blockIdx.x * 256 + t;   // grid covers NN*8
    int n = tid >> 3;
    int p = tid & 7;
    int nl = t >> 3;
    const float4* hp = (const float4*)g_hb;

    int beg = __ldg(&g_rowstart[n]);
    int end = __ldg(&g_rowstart[n + 1]);

    float4 acc = make_float4(0.f, 0.f, 0.f, 0.f);
    int r = beg;
    while (r + 8 <= end) {
        int idx[8];
#pragma unroll
        for (int j = 0; j < 8; j++) idx[j] = __ldg(&g_csrsrc[r + j]);
        float4 hv[8];
#pragma unroll
        for (int j = 0; j < 8; j++) hv[j] = __ldg(hp + (size_t)idx[j] * 8 + p);
        acc = add4(acc, add4(add4(add4(hv[0], hv[1]), add4(hv[2], hv[3])),
                             add4(add4(hv[4], hv[5]), add4(hv[6], hv[7]))));
        r += 8;
    }
    if (r + 4 <= end) {
        int idx[4];
#pragma unroll
        for (int j = 0; j < 4; j++) idx[j] = __ldg(&g_csrsrc[r + j]);
        float4 hv[4];
#pragma unroll
        for (int j = 0; j < 4; j++) hv[j] = __ldg(hp + (size_t)idx[j] * 8 + p);
        acc = add4(acc, add4(add4(hv[0], hv[1]), add4(hv[2], hv[3])));
        r += 4;
    }
    for (; r < end; r++) {
        int s = __ldg(&g_csrsrc[r]);
        acc = add4(acc, __ldg(hp + (size_t)s * 8 + p));
    }
    acc = add4(acc, __ldg(hp + (size_t)n * 8 + p));   // self last

    float dn = g_dinv[n];
    float4 xv;
    xv.x = fmaxf(fmaf(acc.x * dn, sA[4 * p + 0], sB[4 * p + 0]), 0.f);
    xv.y = fmaxf(fmaf(acc.y * dn, sA[4 * p + 1], sB[4 * p + 1]), 0.f);
    xv.z = fmaxf(fmaf(acc.z * dn, sA[4 * p + 2], sB[4 * p + 2]), 0.f);
    xv.w = fmaxf(fmaf(acc.w * dn, sA[4 * p + 3], sB[4 * p + 3]), 0.f);
    *(float4*)(xs + nl * 40 + 4 * p) = xv;
    __syncwarp();   // exchange partners are within this warp only

    const float* xrow = xs + nl * 40;
    unsigned long long a0 = 0ULL, a1 = 0ULL;
#pragma unroll
    for (int k = 0; k < HH; k++) {
        float xk = xrow[k];                  // scalar LDS, conflict-free
        unsigned long long xkk = pk2(xk, xk);
        ulonglong2 w = Ws2[k * 8 + p];
        fma2(a0, xkk, w.x);
        fma2(a1, xkk, w.y);
    }
    unsigned long long dn2 = pk2(dn, dn);
    unsigned long long o0 = mul2(a0, dn2);
    unsigned long long o1 = mul2(a1, dn2);
    ((ulonglong2*)(g_ha + (size_t)n * HH))[p] = make_ulonglong2(o0, o1);
    if (p == 7) {
        float lo, hi;
        asm("mov.b64 {%0,%1}, %2;" : "=f"(lo), "=f"(hi) : "l"(o1));
        g_c31[n] = hi;   // channel 31, bit-identical to g_ha[n*32+31]
    }
}

// ---------------- FUSED SortPool: key gather + sort + top-K full gather -----
__global__ void __launch_bounds__(256) k_sortpool(
    const float* __restrict__ bcp,
    const float* __restrict__ gamma, const float* __restrict__ beta,
    const float* __restrict__ rmean, const float* __restrict__ rvar)
{
    __shared__ unsigned long long keys[CAP];
    __shared__ int ssel[KK];
    __shared__ float sA[HH], sB[HH];
    int b = blockIdx.x, t = threadIdx.x;
    if (t < HH) {
        float sc = gamma[2 * HH + t] * rsqrtf(rvar[2 * HH + t] + EPSF);
        float sh = beta[2 * HH + t] - rmean[2 * HH + t] * sc;
        sA[t] = sc;
        sB[t] = fmaf(bcp[2 * HH + t], sc, sh);
    }
    __syncthreads();

    int start = g_start2[b];
    int cnt = g_start2[b + 1] - start;
    int cc = min(cnt, CAP);
    int size = (cc <= 256) ? 256 : CAP;
    float sc31 = sA[31], sh31 = sB[31];

    // ---- phase 1: compute keys ----
    for (int rr = t; rr < size; rr += 256) {
        unsigned long long key = 0xFFFFFFFFFFFFFFFFull;
        if (rr < cc) {
            int n = start + rr;
            int beg = __ldg(&g_rowstart[n]);
            int end = __ldg(&g_rowstart[n + 1]);
            float acc = 0.f;
            int r = beg;
            while (r + 8 <= end) {
                int idx[8];
#pragma unroll
                for (int j = 0; j < 8; j++) idx[j] = __ldg(&g_csrsrc[r + j]);
                float hv[8];
#pragma unroll
                for (int j = 0; j < 8; j++) hv[j] = __ldg(&g_c31[idx[j]]);
                acc += (((hv[0] + hv[1]) + (hv[2] + hv[3])) +
                        ((hv[4] + hv[5]) + (hv[6] + hv[7])));
                r += 8;
            }
            if (r + 4 <= end) {
                int idx[4];
#pragma unroll
                for (int j = 0; j < 4; j++) idx[j] = __ldg(&g_csrsrc[r + j]);
                float hv[4];
#pragma unroll
                for (int j = 0; j < 4; j++) hv[j] = __ldg(&g_c31[idx[j]]);
                acc += ((hv[0] + hv[1]) + (hv[2] + hv[3]));
                r += 4;
            }
            for (; r < end; r++)
                acc += __ldg(&g_c31[__ldg(&g_csrsrc[r])]);
            acc += __ldg(&g_c31[n]);   // self last

            float v = fmaxf(fmaf(acc * g_dinv[n], sc31, sh31), 0.f);
            unsigned u = (v == 0.0f) ? 0u : __float_as_uint(v);
            key = ((unsigned long long)(~u) << 32) | (unsigned)rr;
        }
        keys[rr] = key;
    }
    __syncthreads();

    // ---- phase 2: bitonic sort ----
    if (size == 256) {
        for (int k = 2; k <= 256; k <<= 1) {
            for (int j = k >> 1; j > 0; j >>= 1) {
                int i = t;
                int ixj = i ^ j;
                if (ixj > i) {
                    unsigned long long a = keys[i], c = keys[ixj];
                    bool up = ((i & k) == 0);
                    bool sw = up ? (a > c) : (a < c);
                    if (sw) { keys[i] = c; keys[ixj] = a; }
                }
                __syncthreads();
            }
        }
    } else {
        for (int k = 2; k <= CAP; k <<= 1) {
            for (int j = k >> 1; j > 0; j >>= 1) {
                for (int base = 0; base < CAP; base += 256) {
                    int i = base + t;
                    int ixj = i ^ j;
                    if (ixj > i) {
                        unsigned long long a = keys[i], c = keys[ixj];
                        bool up = ((i & k) == 0);
                        bool sw = up ? (a > c) : (a < c);
                        if (sw) { keys[i] = c; keys[ixj] = a; }
                    }
                }
                __syncthreads();
            }
        }
    }

    int nval = min(cc, KK);
    if (t < KK)
        ssel[t] = (t < nval) ? start + (int)(unsigned)(keys[t] & 0xFFFFFFFFu) : -1;
    __syncthreads();

    // ---- phase 3: full gather for selected nodes ----
    if (t < KK * 8) {
        int slot = t >> 3;
        int p = t & 7;
        int n = ssel[slot];
        float4* outp = (float4*)(g_pooled + (size_t)(b * KK + slot) * HH) + p;
        if (n < 0) {
            *outp = make_float4(0.f, 0.f, 0.f, 0.f);
        } else {
            const float4* hp = (const float4*)g_ha;
            int beg = __ldg(&g_rowstart[n]);
            int end = __ldg(&g_rowstart[n + 1]);
            float4 acc = make_float4(0.f, 0.f, 0.f, 0.f);
            int r = beg;
            while (r + 8 <= end) {
                int idx[8];
#pragma unroll
                for (int j = 0; j < 8; j++) idx[j] = __ldg(&g_csrsrc[r + j]);
                float4 hv[8];
#pragma unroll
                for (int j = 0; j < 8; j++) hv[j] = __ldg(hp + (size_t)idx[j] * 8 + p);
                acc = add4(acc, add4(add4(add4(hv[0], hv[1]), add4(hv[2], hv[3])),
                                     add4(add4(hv[4], hv[5]), add4(hv[6], hv[7]))));
                r += 8;
            }
            if (r + 4 <= end) {
                int idx[4];
#pragma unroll
                for (int j = 0; j < 4; j++) idx[j] = __ldg(&g_csrsrc[r + j]);
                float4 hv[4];
#pragma unroll
                for (int j = 0; j < 4; j++) hv[j] = __ldg(hp + (size_t)idx[j] * 8 + p);
                acc = add4(acc, add4(add4(hv[0], hv[1]), add4(hv[2], hv[3])));
                r += 4;
            }
            for (; r < end; r++) {
                int s = __ldg(&g_csrsrc[r]);
                acc = add4(acc, __ldg(hp + (size_t)s * 8 + p));
            }
            acc = add4(acc, __ldg(hp + (size_t)n * 8 + p));   // self last

            float dn = g_dinv[n];
            float4 xv;
            xv.x = fmaxf(fmaf(acc.x * dn, sA[4 * p + 0], sB[4 * p + 0]), 0.f);
            xv.y = fmaxf(fmaf(acc.y * dn, sA[4 * p + 1], sB[4 * p + 1]), 0.f);
            xv.z = fmaxf(fmaf(acc.z * dn, sA[4 * p + 2], sB[4 * p + 2]), 0.f);
            xv.w = fmaxf(fmaf(acc.w * dn, sA[4 * p + 3], sB[4 * p + 3]), 0.f);
            *outp = xv;
        }
    }
}

// ---------------- MLP head: block-tiled, 32 graphs/block --------------------
__global__ void __launch_bounds__(256) k_mlp(
    const float* __restrict__ W1, const float* __restrict__ b1,
    const float* __restrict__ W2, const float* __restrict__ b2,
    const float* __restrict__ W3, const float* __restrict__ b3,
    float* __restrict__ out)
{
    __shared__ float  Xs[32][33];
    __shared__ float4 Wt[32][8];
    __shared__ float  H1[32][33];
    int t = threadIdx.x;
    int tg = t >> 3, tj = t & 7;
    int g0 = blockIdx.x * 32;

    float4 accf = __ldg((const float4*)b1 + tj);
    unsigned long long a0 = pk2(accf.x, accf.y);
    unsigned long long a1 = pk2(accf.z, accf.w);

    for (int c = 0; c < 30; c++) {
        int p0 = c * 32;
        __syncthreads();
        float4 xv = __ldg((const float4*)(g_pooled + (size_t)(g0 + tg) * (KK * HH)
                                          + p0 + 4 * tj));
        Xs[tg][4 * tj + 0] = xv.x; Xs[tg][4 * tj + 1] = xv.y;
        Xs[tg][4 * tj + 2] = xv.z; Xs[tg][4 * tj + 3] = xv.w;
        Wt[tg][tj] = __ldg((const float4*)(W1 + (size_t)(p0 + tg) * 32 + 4 * tj));
        __syncthreads();
#pragma unroll
        for (int kk = 0; kk < 32; kk++) {
            float xk = Xs[tg][kk];
            unsigned long long xkk = pk2(xk, xk);
            float4 w = Wt[kk][tj];
            fma2(a0, xkk, pk2(w.x, w.y));
            fma2(a1, xkk, pk2(w.z, w.w));
        }
    }
    float r0, r1, r2, r3;
    asm("mov.b64 {%0,%1}, %2;" : "=f"(r0), "=f"(r1) : "l"(a0));
    asm("mov.b64 {%0,%1}, %2;" : "=f"(r2), "=f"(r3) : "l"(a1));
    H1[tg][4 * tj + 0] = fmaxf(r0, 0.f);
    H1[tg][4 * tj + 1] = fmaxf(r1, 0.f);
    H1[tg][4 * tj + 2] = fmaxf(r2, 0.f);
    H1[tg][4 * tj + 3] = fmaxf(r3, 0.f);
    __syncthreads();

    if (t < 32) {
        int g = t;
        float h2a[16];
#pragma unroll
        for (int m = 0; m < 16; m++) h2a[m] = b2[m];
#pragma unroll
        for (int h = 0; h < 32; h++) {
            float x = H1[g][h];
#pragma unroll
            for (int m = 0; m < 16; m++) h2a[m] = fmaf(x, W2[h * 16 + m], h2a[m]);
        }
        float o = b3[0];
#pragma unroll
        for (int m = 0; m < 16; m++) o = fmaf(fmaxf(h2a[m], 0.f), W3[m], o);
        out[g0 + g] = o;
    }
}

// ---------------- launch -----------------------------------------------------
extern "C" void kernel_launch(void* const* d_in, const int* in_sizes, int n_in,
                              void* d_out, int out_size) {
    const int*   xz    = (const int*)d_in[0];
    const int*   ei    = (const int*)d_in[1];
    const int*   batch = (const int*)d_in[2];
    const float* emb   = (const float*)d_in[3];
    const float* Wc    = (const float*)d_in[4];
    const float* bc    = (const float*)d_in[5];
    const float* gamma = (const float*)d_in[6];
    const float* beta  = (const float*)d_in[7];
    const float* rmean = (const float*)d_in[8];
    const float* rvar  = (const float*)d_in[9];
    const float* W1    = (const float*)d_in[10];
    const float* b1    = (const float*)d_in[11];
    const float* W2    = (const float*)d_in[12];
    const float* b2    = (const float*)d_in[13];
    const float* W3    = (const float*)d_in[14];
    const float* b3    = (const float*)d_in[15];
    float* out = (float*)d_out;

    const int* src = ei;
    const int* dst = ei + EE;

    void* degptr = nullptr;
    cudaGetSymbolAddress(&degptr, g_deg);
    cudaMemsetAsync(degptr, 0, NN * sizeof(int));                         // 1

    k_degb    <<<EE / 1024, 256>>>(dst);                                  // 2
    k_scanA   <<<NBLK, 256>>>(xz, batch);                                 // 3
    k_scanB   <<<NBLK, 256>>>();                                          // 4
    k_fill    <<<EE / 1024, 256>>>(src, dst);                             // 5
    k_sortval <<<NBLK, 256>>>();                                          // 6
    k_embw    <<<(MAXZ1 + 7) / 8, 256>>>(emb, Wc);                        // 7
    k_gbg0    <<<(NN * 8) / 256, 256>>>(Wc, bc, gamma, beta, rmean, rvar);// 8
    k_gbg     <<<(NN * 8) / 256, 256>>>(Wc, bc, gamma, beta, rmean, rvar);// 9
    k_sortpool<<<BB, 256>>>(bc, gamma, beta, rmean, rvar);                // 10
    k_mlp     <<<BB / 32, 256>>>(W1, b1, W2, b2, W3, b3, out);            // 11
}

// round 17
// speedup vs baseline: 1.0832x; 1.0113x over previous
#include <cuda_runtime.h>

#define NN 524288
#define EE 4194304
#define BB 4096
#define HH 32
#define KK 30
#define CAP 512
#define MAXZ1 1001
#define EPSF 1e-5f
#define NBLK 2048          // NN/256

// ---------------- scratch (device globals; no allocation allowed) ----------
__device__ int   g_deg[NN];
__device__ float g_dinv[NN];
__device__ int2  g_pack[NN];              // {xz, dinv bits}
__device__ float g_embw[MAXZ1 * HH];      // emb @ W0   (128KB)
__device__ float g_ha[(size_t)NN * HH];   // layer1 out
__device__ float g_hb[(size_t)NN * HH];   // layer0 out
__device__ float g_c31[NN];               // h' channel 31 sidecar (L2-resident)
__device__ int   g_rowstart[NN + 1];
__device__ unsigned g_rank4[EE / 4];      // per-edge rank, uchar4-packed
__device__ int   g_csrsrc[EE];
__device__ int   g_bsum[NBLK];
__device__ int   g_start2[BB + 1];
__device__ float g_pooled[(size_t)BB * KK * HH];

__device__ __forceinline__ float4 add4(float4 a, float4 b) {
    return make_float4(a.x + b.x, a.y + b.y, a.z + b.z, a.w + b.w);
}
__device__ __forceinline__ float4 scale4(float4 a, float s) {
    return make_float4(a.x * s, a.y * s, a.z * s, a.w * s);
}
__device__ __forceinline__ unsigned long long pk2(float x, float y) {
    unsigned long long r;
    asm("mov.b64 %0, {%1,%2};" : "=l"(r) : "f"(x), "f"(y));
    return r;
}
__device__ __forceinline__ void fma2(unsigned long long& d, unsigned long long a,
                                     unsigned long long b) {
    asm("fma.rn.f32x2 %0, %1, %2, %0;" : "+l"(d) : "l"(a), "l"(b));
}
__device__ __forceinline__ unsigned long long mul2(unsigned long long a,
                                                   unsigned long long b) {
    unsigned long long r;
    asm("mul.rn.f32x2 %0, %1, %2;" : "=l"(r) : "l"(a), "l"(b));
    return r;
}

// in-degree histogram + packed per-edge rank, 4 edges/thread
__global__ void k_degb(const int* __restrict__ dst) {
    int i = blockIdx.x * 256 + threadIdx.x;   // grid covers EE/4
    int4 d = ((const int4*)dst)[i];
    unsigned r0 = (unsigned)atomicAdd(&g_deg[d.x], 1);
    unsigned r1 = (unsigned)atomicAdd(&g_deg[d.y], 1);
    unsigned r2 = (unsigned)atomicAdd(&g_deg[d.z], 1);
    unsigned r3 = (unsigned)atomicAdd(&g_deg[d.w], 1);
    g_rank4[i] = (r0 & 0xFFu) | ((r1 & 0xFFu) << 8) |
                 ((r2 & 0xFFu) << 16) | ((r3 & 0xFFu) << 24);
}

// scanA: block sums of deg + dinv + pack{xz,dinv} + graph boundaries
__global__ void k_scanA(const int* __restrict__ xz, const int* __restrict__ batch) {
    __shared__ int s[256];
    int t = threadIdx.x;
    int i = blockIdx.x * 256 + t;
    int d = g_deg[i];
    float dn = rsqrtf((float)d + 1.0f);
    g_dinv[i] = dn;
    g_pack[i] = make_int2(xz[i], __float_as_int(dn));
    {
        int b1 = batch[i];
        int b0 = (i > 0) ? batch[i - 1] : -1;
        for (int b = b0 + 1; b <= b1; b++) g_start2[b] = i;
        if (i == NN - 1)
            for (int b = b1 + 1; b <= BB; b++) g_start2[b] = NN;
    }
    s[t] = d;
    __syncthreads();
    for (int off = 128; off; off >>= 1) {
        if (t < off) s[t] += s[t + off];
        __syncthreads();
    }
    if (t == 0) g_bsum[blockIdx.x] = s[0];
}

// scanB: each block sums its bsum prefix directly, then local scan
__global__ void __launch_bounds__(256) k_scanB() {
    __shared__ int red[256];
    __shared__ int s[256];
    int b = blockIdx.x, t = threadIdx.x;
    int part = 0;
    for (int j = t; j < b; j += 256) part += g_bsum[j];
    red[t] = part;
    __syncthreads();
    for (int off = 128; off; off >>= 1) {
        if (t < off) red[t] += red[t + off];
        __syncthreads();
    }
    int base = red[0];
    int i = b * 256 + t;
    int d = g_deg[i];
    s[t] = d;
    __syncthreads();
    for (int off = 1; off < 256; off <<= 1) {
        int v = (t >= off) ? s[t - off] : 0;
        __syncthreads();
        s[t] += v;
        __syncthreads();
    }
    int excl = base + s[t] - d;
    g_rowstart[i] = excl;
    if (i == NN - 1) g_rowstart[NN] = EE;
}

// ---------------- CSR fill: NO atomics (pos = rowstart[dst] + rank[e]) ------
__global__ void k_fill(const int* __restrict__ src, const int* __restrict__ dst) {
    int i = blockIdx.x * 256 + threadIdx.x;   // grid covers EE/4
    int4 sv = ((const int4*)src)[i];
    int4 dv = ((const int4*)dst)[i];
    unsigned rk = g_rank4[i];
    g_csrsrc[__ldg(&g_rowstart[dv.x]) + (int)(rk & 0xFFu)] = sv.x;
    g_csrsrc[__ldg(&g_rowstart[dv.y]) + (int)((rk >> 8) & 0xFFu)] = sv.y;
    g_csrsrc[__ldg(&g_rowstart[dv.z]) + (int)((rk >> 16) & 0xFFu)] = sv.z;
    g_csrsrc[__ldg(&g_rowstart[dv.w]) + (int)(rk >> 24)] = sv.w;
}

// ---------------- merged: canonicalize rows (blocks < NBLK) + embW0 ---------
__global__ void __launch_bounds__(256) k_sortemb(
    const float* __restrict__ emb, const float* __restrict__ Wc)
{
    int b = blockIdx.x, t = threadIdx.x;
    if (b < NBLK) {
        // sort each row's src values ascending (canonical deterministic order)
        int n = b * 256 + t;
        int beg = g_rowstart[n];
        int len = g_rowstart[n + 1] - beg;
        if (len <= 1) return;
        if (len <= 16) {
            int v[16];
#pragma unroll
            for (int i = 0; i < 16; i++)
                v[i] = (i < len) ? g_csrsrc[beg + i] : 0x7FFFFFFF;
#pragma unroll
            for (int k = 2; k <= 16; k <<= 1) {
#pragma unroll
                for (int j = k >> 1; j > 0; j >>= 1) {
#pragma unroll
                    for (int i = 0; i < 16; i++) {
                        int ix = i ^ j;
                        if (ix > i) {
                            bool up = ((i & k) == 0);
                            int a = v[i], c = v[ix];
                            bool sw = up ? (a > c) : (a < c);
                            if (sw) { v[i] = c; v[ix] = a; }
                        }
                    }
                }
            }
            for (int i = 0; i < len; i++) g_csrsrc[beg + i] = v[i];
        } else {
            int end = beg + len;
            for (int i = beg + 1; i < end; i++) {
                int key = g_csrsrc[i];
                int j = i - 1;
                while (j >= beg && g_csrsrc[j] > key) {
                    g_csrsrc[j + 1] = g_csrsrc[j];
                    j--;
                }
                g_csrsrc[j + 1] = key;
            }
        }
    } else {
        // embW0 = emb @ Wc[0]
        __shared__ float Ws[HH * HH];
        int bb = b - NBLK;
        for (int i = t; i < HH * HH; i += 256) Ws[i] = Wc[i];
        __syncthreads();
        int row = bb * 8 + (t >> 5);
        int col = t & 31;
        if (row < MAXZ1) {
            const float* er = emb + (size_t)row * HH;
            float acc = 0.f;
#pragma unroll
            for (int k = 0; k < HH; k++) acc = fmaf(er[k], Ws[k * HH + col], acc);
            g_embw[row * HH + col] = acc;
        }
    }
}

// ---------------- layer 0 fused: table-gather + BN0 + ReLU + GEMM1 ----------
__global__ void __launch_bounds__(256) k_gbg0(
    const float* __restrict__ Wc, const float* __restrict__ bcp,
    const float* __restrict__ gamma, const float* __restrict__ beta,
    const float* __restrict__ rmean, const float* __restrict__ rvar)
{
    __shared__ ulonglong2 Ws2[HH * 8];
    __shared__ float sA[HH], sB[HH];
    __shared__ float xs[32 * 40];
    int t = threadIdx.x;
    if (t < HH * 8) Ws2[t] = ((const ulonglong2*)(Wc + 1 * HH * HH))[t];
    if (t < HH) {
        float sc = gamma[t] * rsqrtf(rvar[t] + EPSF);
        float sh = beta[t] - rmean[t] * sc;
        sA[t] = sc;
        sB[t] = fmaf(bcp[t], sc, sh);
    }
    __syncthreads();

    int tid = blockIdx.x * 256 + t;   // grid covers NN*8
    int n = tid >> 3;
    int p = tid & 7;
    int nl = t >> 3;
    const float4* ew = (const float4*)g_embw;

    int beg = __ldg(&g_rowstart[n]);
    int end = __ldg(&g_rowstart[n + 1]);

    float4 acc = make_float4(0.f, 0.f, 0.f, 0.f);
    int r = beg;
    while (r + 8 <= end) {
        int idx[8];
#pragma unroll
        for (int j = 0; j < 8; j++) idx[j] = __ldg(&g_csrsrc[r + j]);
        int2 pk[8];
#pragma unroll
        for (int j = 0; j < 8; j++) pk[j] = __ldg(&g_pack[idx[j]]);
        float4 hv[8];
#pragma unroll
        for (int j = 0; j < 8; j++)
            hv[j] = scale4(__ldg(ew + (size_t)pk[j].x * 8 + p),
                           __int_as_float(pk[j].y));
        acc = add4(acc, add4(add4(add4(hv[0], hv[1]), add4(hv[2], hv[3])),
                             add4(add4(hv[4], hv[5]), add4(hv[6], hv[7]))));
        r += 8;
    }
    if (r + 4 <= end) {
        int idx[4];
#pragma unroll
        for (int j = 0; j < 4; j++) idx[j] = __ldg(&g_csrsrc[r + j]);
        int2 pk[4];
#pragma unroll
        for (int j = 0; j < 4; j++) pk[j] = __ldg(&g_pack[idx[j]]);
        float4 hv[4];
#pragma unroll
        for (int j = 0; j < 4; j++)
            hv[j] = scale4(__ldg(ew + (size_t)pk[j].x * 8 + p),
                           __int_as_float(pk[j].y));
        acc = add4(acc, add4(add4(hv[0], hv[1]), add4(hv[2], hv[3])));
        r += 4;
    }
    for (; r < end; r++) {
        int s = __ldg(&g_csrsrc[r]);
        int2 pk = __ldg(&g_pack[s]);
        acc = add4(acc, scale4(__ldg(ew + (size_t)pk.x * 8 + p),
                               __int_as_float(pk.y)));
    }
    // self term last (matches reference order)
    int2 pks = __ldg(&g_pack[n]);
    float dn = __int_as_float(pks.y);
    acc = add4(acc, scale4(__ldg(ew + (size_t)pks.x * 8 + p), dn));

    float4 xv;
    xv.x = fmaxf(fmaf(acc.x * dn, sA[4 * p + 0], sB[4 * p + 0]), 0.f);
    xv.y = fmaxf(fmaf(acc.y * dn, sA[4 * p + 1], sB[4 * p + 1]), 0.f);
    xv.z = fmaxf(fmaf(acc.z * dn, sA[4 * p + 2], sB[4 * p + 2]), 0.f);
    xv.w = fmaxf(fmaf(acc.w * dn, sA[4 * p + 3], sB[4 * p + 3]), 0.f);
    *(float4*)(xs + nl * 40 + 4 * p) = xv;
    __syncwarp();   // exchange partners are within this warp only

    const float* xrow = xs + nl * 40;
    unsigned long long a0 = 0ULL, a1 = 0ULL;
#pragma unroll
    for (int k = 0; k < HH; k++) {
        float xk = xrow[k];                  // scalar LDS, conflict-free
        unsigned long long xkk = pk2(xk, xk);
        ulonglong2 w = Ws2[k * 8 + p];
        fma2(a0, xkk, w.x);
        fma2(a1, xkk, w.y);
    }
    unsigned long long dn2 = pk2(dn, dn);
    ((ulonglong2*)(g_hb + (size_t)n * HH))[p] =
        make_ulonglong2(mul2(a0, dn2), mul2(a1, dn2));
}

// ---------------- layer 1 fused: gather(hb) + BN1 + ReLU + GEMM2 -> ha ------
// Also writes channel-31 sidecar g_c31 (bit-identical value).
__global__ void __launch_bounds__(256) k_gbg(
    const float* __restrict__ Wc, const float* __restrict__ bcp,
    const float* __restrict__ gamma, const float* __restrict__ beta,
    const float* __restrict__ rmean, const float* __restrict__ rvar)
{
    __shared__ ulonglong2 Ws2[HH * 8];
    __shared__ float sA[HH], sB[HH];
    __shared__ float xs[32 * 40];
    int t = threadIdx.x;
    if (t < HH * 8) Ws2[t] = ((const ulonglong2*)(Wc + 2 * HH * HH))[t];
    if (t < HH) {
        float sc = gamma[HH + t] * rsqrtf(rvar[HH + t] + EPSF);
        float sh = beta[HH + t] - rmean[HH + t] * sc;
        sA[t] = sc;
        sB[t] = fmaf(bcp[HH + t], sc, sh);
    }
    __syncthreads();

    int tid = blockIdx.x * 256 + t;   // grid covers NN*8
    int n = tid >> 3;
    int p = tid & 7;
    int nl = t >> 3;
    const float4* hp = (const float4*)g_hb;

    int beg = __ldg(&g_rowstart[n]);
    int end = __ldg(&g_rowstart[n + 1]);

    float4 acc = make_float4(0.f, 0.f, 0.f, 0.f);
    int r = beg;
    while (r + 8 <= end) {
        int idx[8];
#pragma unroll
        for (int j = 0; j < 8; j++) idx[j] = __ldg(&g_csrsrc[r + j]);
        float4 hv[8];
#pragma unroll
        for (int j = 0; j < 8; j++) hv[j] = __ldg(hp + (size_t)idx[j] * 8 + p);
        acc = add4(acc, add4(add4(add4(hv[0], hv[1]), add4(hv[2], hv[3])),
                             add4(add4(hv[4], hv[5]), add4(hv[6], hv[7]))));
        r += 8;
    }
    if (r + 4 <= end) {
        int idx[4];
#pragma unroll
        for (int j = 0; j < 4; j++) idx[j] = __ldg(&g_csrsrc[r + j]);
        float4 hv[4];
#pragma unroll
        for (int j = 0; j < 4; j++) hv[j] = __ldg(hp + (size_t)idx[j] * 8 + p);
        acc = add4(acc, add4(add4(hv[0], hv[1]), add4(hv[2], hv[3])));
        r += 4;
    }
    for (; r < end; r++) {
        int s = __ldg(&g_csrsrc[r]);
        acc = add4(acc, __ldg(hp + (size_t)s * 8 + p));
    }
    acc = add4(acc, __ldg(hp + (size_t)n * 8 + p));   // self last

    float dn = g_dinv[n];
    float4 xv;
    xv.x = fmaxf(fmaf(acc.x * dn, sA[4 * p + 0], sB[4 * p + 0]), 0.f);
    xv.y = fmaxf(fmaf(acc.y * dn, sA[4 * p + 1], sB[4 * p + 1]), 0.f);
    xv.z = fmaxf(fmaf(acc.z * dn, sA[4 * p + 2], sB[4 * p + 2]), 0.f);
    xv.w = fmaxf(fmaf(acc.w * dn, sA[4 * p + 3], sB[4 * p + 3]), 0.f);
    *(float4*)(xs + nl * 40 + 4 * p) = xv;
    __syncwarp();   // exchange partners are within this warp only

    const float* xrow = xs + nl * 40;
    unsigned long long a0 = 0ULL, a1 = 0ULL;
#pragma unroll
    for (int k = 0; k < HH; k++) {
        float xk = xrow[k];                  // scalar LDS, conflict-free
        unsigned long long xkk = pk2(xk, xk);
        ulonglong2 w = Ws2[k * 8 + p];
        fma2(a0, xkk, w.x);
        fma2(a1, xkk, w.y);
    }
    unsigned long long dn2 = pk2(dn, dn);
    unsigned long long o0 = mul2(a0, dn2);
    unsigned long long o1 = mul2(a1, dn2);
    ((ulonglong2*)(g_ha + (size_t)n * HH))[p] = make_ulonglong2(o0, o1);
    if (p == 7) {
        float lo, hi;
        asm("mov.b64 {%0,%1}, %2;" : "=f"(lo), "=f"(hi) : "l"(o1));
        g_c31[n] = hi;   // channel 31, bit-identical to g_ha[n*32+31]
    }
}

// ---------------- FUSED SortPool: key gather + sort + top-K full gather -----
__global__ void __launch_bounds__(256) k_sortpool(
    const float* __restrict__ bcp,
    const float* __restrict__ gamma, const float* __restrict__ beta,
    const float* __restrict__ rmean, const float* __restrict__ rvar)
{
    __shared__ unsigned long long keys[CAP];
    __shared__ int ssel[KK];
    __shared__ float sA[HH], sB[HH];
    int b = blockIdx.x, t = threadIdx.x;
    if (t < HH) {
        float sc = gamma[2 * HH + t] * rsqrtf(rvar[2 * HH + t] + EPSF);
        float sh = beta[2 * HH + t] - rmean[2 * HH + t] * sc;
        sA[t] = sc;
        sB[t] = fmaf(bcp[2 * HH + t], sc, sh);
    }
    __syncthreads();

    int start = g_start2[b];
    int cnt = g_start2[b + 1] - start;
    int cc = min(cnt, CAP);
    int size = (cc <= 256) ? 256 : CAP;
    float sc31 = sA[31], sh31 = sB[31];

    // ---- phase 1: compute keys ----
    for (int rr = t; rr < size; rr += 256) {
        unsigned long long key = 0xFFFFFFFFFFFFFFFFull;
        if (rr < cc) {
            int n = start + rr;
            int beg = __ldg(&g_rowstart[n]);
            int end = __ldg(&g_rowstart[n + 1]);
            float acc = 0.f;
            int r = beg;
            while (r + 8 <= end) {
                int idx[8];
#pragma unroll
                for (int j = 0; j < 8; j++) idx[j] = __ldg(&g_csrsrc[r + j]);
                float hv[8];
#pragma unroll
                for (int j = 0; j < 8; j++) hv[j] = __ldg(&g_c31[idx[j]]);
                acc += (((hv[0] + hv[1]) + (hv[2] + hv[3])) +
                        ((hv[4] + hv[5]) + (hv[6] + hv[7])));
                r += 8;
            }
            if (r + 4 <= end) {
                int idx[4];
#pragma unroll
                for (int j = 0; j < 4; j++) idx[j] = __ldg(&g_csrsrc[r + j]);
                float hv[4];
#pragma unroll
                for (int j = 0; j < 4; j++) hv[j] = __ldg(&g_c31[idx[j]]);
                acc += ((hv[0] + hv[1]) + (hv[2] + hv[3]));
                r += 4;
            }
            for (; r < end; r++)
                acc += __ldg(&g_c31[__ldg(&g_csrsrc[r])]);
            acc += __ldg(&g_c31[n]);   // self last

            float v = fmaxf(fmaf(acc * g_dinv[n], sc31, sh31), 0.f);
            unsigned u = (v == 0.0f) ? 0u : __float_as_uint(v);
            key = ((unsigned long long)(~u) << 32) | (unsigned)rr;
        }
        keys[rr] = key;
    }
    __syncthreads();

    // ---- phase 2: bitonic sort ----
    if (size == 256) {
        for (int k = 2; k <= 256; k <<= 1) {
            for (int j = k >> 1; j > 0; j >>= 1) {
                int i = t;
                int ixj = i ^ j;
                if (ixj > i) {
                    unsigned long long a = keys[i], c = keys[ixj];
                    bool up = ((i & k) == 0);
                    bool sw = up ? (a > c) : (a < c);
                    if (sw) { keys[i] = c; keys[ixj] = a; }
                }
                __syncthreads();
            }
        }
    } else {
        for (int k = 2; k <= CAP; k <<= 1) {
            for (int j = k >> 1; j > 0; j >>= 1) {
                for (int base = 0; base < CAP; base += 256) {
                    int i = base + t;
                    int ixj = i ^ j;
                    if (ixj > i) {
                        unsigned long long a = keys[i], c = keys[ixj];
                        bool up = ((i & k) == 0);
                        bool sw = up ? (a > c) : (a < c);
                        if (sw) { keys[i] = c; keys[ixj] = a; }
                    }
                }
                __syncthreads();
            }
        }
    }

    int nval = min(cc, KK);
    if (t < KK)
        ssel[t] = (t < nval) ? start + (int)(unsigned)(keys[t] & 0xFFFFFFFFu) : -1;
    __syncthreads();

    // ---- phase 3: full gather for selected nodes ----
    if (t < KK * 8) {
        int slot = t >> 3;
        int p = t & 7;
        int n = ssel[slot];
        float4* outp = (float4*)(g_pooled + (size_t)(b * KK + slot) * HH) + p;
        if (n < 0) {
            *outp = make_float4(0.f, 0.f, 0.f, 0.f);
        } else {
            const float4* hp = (const float4*)g_ha;
            int beg = __ldg(&g_rowstart[n]);
            int end = __ldg(&g_rowstart[n + 1]);
            float4 acc = make_float4(0.f, 0.f, 0.f, 0.f);
            int r = beg;
            while (r + 8 <= end) {
                int idx[8];
#pragma unroll
                for (int j = 0; j < 8; j++) idx[j] = __ldg(&g_csrsrc[r + j]);
                float4 hv[8];
#pragma unroll
                for (int j = 0; j < 8; j++) hv[j] = __ldg(hp + (size_t)idx[j] * 8 + p);
                acc = add4(acc, add4(add4(add4(hv[0], hv[1]), add4(hv[2], hv[3])),
                                     add4(add4(hv[4], hv[5]), add4(hv[6], hv[7]))));
                r += 8;
            }
            if (r + 4 <= end) {
                int idx[4];
#pragma unroll
                for (int j = 0; j < 4; j++) idx[j] = __ldg(&g_csrsrc[r + j]);
                float4 hv[4];
#pragma unroll
                for (int j = 0; j < 4; j++) hv[j] = __ldg(hp + (size_t)idx[j] * 8 + p);
                acc = add4(acc, add4(add4(hv[0], hv[1]), add4(hv[2], hv[3])));
                r += 4;
            }
            for (; r < end; r++) {
                int s = __ldg(&g_csrsrc[r]);
                acc = add4(acc, __ldg(hp + (size_t)s * 8 + p));
            }
            acc = add4(acc, __ldg(hp + (size_t)n * 8 + p));   // self last

            float dn = g_dinv[n];
            float4 xv;
            xv.x = fmaxf(fmaf(acc.x * dn, sA[4 * p + 0], sB[4 * p + 0]), 0.f);
            xv.y = fmaxf(fmaf(acc.y * dn, sA[4 * p + 1], sB[4 * p + 1]), 0.f);
            xv.z = fmaxf(fmaf(acc.z * dn, sA[4 * p + 2], sB[4 * p + 2]), 0.f);
            xv.w = fmaxf(fmaf(acc.w * dn, sA[4 * p + 3], sB[4 * p + 3]), 0.f);
            *outp = xv;
        }
    }
}

// ---------------- MLP head: block-tiled, 32 graphs/block --------------------
__global__ void __launch_bounds__(256) k_mlp(
    const float* __restrict__ W1, const float* __restrict__ b1,
    const float* __restrict__ W2, const float* __restrict__ b2,
    const float* __restrict__ W3, const float* __restrict__ b3,
    float* __restrict__ out)
{
    __shared__ float  Xs[32][33];
    __shared__ float4 Wt[32][8];
    __shared__ float  H1[32][33];
    int t = threadIdx.x;
    int tg = t >> 3, tj = t & 7;
    int g0 = blockIdx.x * 32;

    float4 accf = __ldg((const float4*)b1 + tj);
    unsigned long long a0 = pk2(accf.x, accf.y);
    unsigned long long a1 = pk2(accf.z, accf.w);

    for (int c = 0; c < 30; c++) {
        int p0 = c * 32;
        __syncthreads();
        float4 xv = __ldg((const float4*)(g_pooled + (size_t)(g0 + tg) * (KK * HH)
                                          + p0 + 4 * tj));
        Xs[tg][4 * tj + 0] = xv.x; Xs[tg][4 * tj + 1] = xv.y;
        Xs[tg][4 * tj + 2] = xv.z; Xs[tg][4 * tj + 3] = xv.w;
        Wt[tg][tj] = __ldg((const float4*)(W1 + (size_t)(p0 + tg) * 32 + 4 * tj));
        __syncthreads();
#pragma unroll
        for (int kk = 0; kk < 32; kk++) {
            float xk = Xs[tg][kk];
            unsigned long long xkk = pk2(xk, xk);
            float4 w = Wt[kk][tj];
            fma2(a0, xkk, pk2(w.x, w.y));
            fma2(a1, xkk, pk2(w.z, w.w));
        }
    }
    float r0, r1, r2, r3;
    asm("mov.b64 {%0,%1}, %2;" : "=f"(r0), "=f"(r1) : "l"(a0));
    asm("mov.b64 {%0,%1}, %2;" : "=f"(r2), "=f"(r3) : "l"(a1));
    H1[tg][4 * tj + 0] = fmaxf(r0, 0.f);
    H1[tg][4 * tj + 1] = fmaxf(r1, 0.f);
    H1[tg][4 * tj + 2] = fmaxf(r2, 0.f);
    H1[tg][4 * tj + 3] = fmaxf(r3, 0.f);
    __syncthreads();

    if (t < 32) {
        int g = t;
        float h2a[16];
#pragma unroll
        for (int m = 0; m < 16; m++) h2a[m] = b2[m];
#pragma unroll
        for (int h = 0; h < 32; h++) {
            float x = H1[g][h];
#pragma unroll
            for (int m = 0; m < 16; m++) h2a[m] = fmaf(x, W2[h * 16 + m], h2a[m]);
        }
        float o = b3[0];
#pragma unroll
        for (int m = 0; m < 16; m++) o = fmaf(fmaxf(h2a[m], 0.f), W3[m], o);
        out[g0 + g] = o;
    }
}

// ---------------- launch -----------------------------------------------------
extern "C" void kernel_launch(void* const* d_in, const int* in_sizes, int n_in,
                              void* d_out, int out_size) {
    const int*   xz    = (const int*)d_in[0];
    const int*   ei    = (const int*)d_in[1];
    const int*   batch = (const int*)d_in[2];
    const float* emb   = (const float*)d_in[3];
    const float* Wc    = (const float*)d_in[4];
    const float* bc    = (const float*)d_in[5];
    const float* gamma = (const float*)d_in[6];
    const float* beta  = (const float*)d_in[7];
    const float* rmean = (const float*)d_in[8];
    const float* rvar  = (const float*)d_in[9];
    const float* W1    = (const float*)d_in[10];
    const float* b1    = (const float*)d_in[11];
    const float* W2    = (const float*)d_in[12];
    const float* b2    = (const float*)d_in[13];
    const float* W3    = (const float*)d_in[14];
    const float* b3    = (const float*)d_in[15];
    float* out = (float*)d_out;

    const int* src = ei;
    const int* dst = ei + EE;

    void* degptr = nullptr;
    cudaGetSymbolAddress(&degptr, g_deg);
    cudaMemsetAsync(degptr, 0, NN * sizeof(int));                         // 1

    k_degb    <<<EE / 1024, 256>>>(dst);                                  // 2
    k_scanA   <<<NBLK, 256>>>(xz, batch);                                 // 3
    k_scanB   <<<NBLK, 256>>>();                                          // 4
    k_fill    <<<EE / 1024, 256>>>(src, dst);                             // 5
    k_sortemb <<<NBLK + 126, 256>>>(emb, Wc);                             // 6
    k_gbg0    <<<(NN * 8) / 256, 256>>>(Wc, bc, gamma, beta, rmean, rvar);// 7
    k_gbg     <<<(NN * 8) / 256, 256>>>(Wc, bc, gamma, beta, rmean, rvar);// 8
    k_sortpool<<<BB, 256>>>(bc, gamma, beta, rmean, rvar);                // 9
    k_mlp     <<<BB / 32, 256>>>(W1, b1, W2, b2, W3, b3, out);            // 10
}